// round 1
// baseline (speedup 1.0000x reference)
#include <cuda_runtime.h>
#include <cuda_bf16.h>

// Model dims
#define BB 2
#define SS 2048
#define DD 512
#define LL 6
#define HH 8
#define DH 64
#define FF 2048
#define VV 32000
#define ROWS (BB*SS)   // 4096

// Scratch (device globals: no allocations allowed)
__device__ float g_h  [ROWS * DD];   // hidden state
__device__ float g_big[ROWS * FF];   // qkv (4096x1536) / ff1 out (4096x2048)
__device__ float g_o  [ROWS * DD];   // attention output
__device__ float g_t  [ROWS * DD];   // pre-LN gemm output / final LN

// ---------------------------------------------------------------------------
// Embedding + positional encoding
// ---------------------------------------------------------------------------
__global__ void embed_k(const int* __restrict__ x, const float* __restrict__ emb,
                        const float* __restrict__ pe, float* __restrict__ h)
{
    int row = blockIdx.x;            // b*S + s
    int s   = row & (SS - 1);
    int tok = x[row];
    const float4* e = (const float4*)(emb + (long)tok * DD);
    const float4* p = (const float4*)(pe  + (long)s   * DD);
    float4 ev = e[threadIdx.x], pv = p[threadIdx.x];
    float4 o;
    o.x = ev.x + pv.x; o.y = ev.y + pv.y; o.z = ev.z + pv.z; o.w = ev.w + pv.w;
    ((float4*)(h + (long)row * DD))[threadIdx.x] = o;
}

// ---------------------------------------------------------------------------
// SGEMM: C[M,N] = A[M,K] @ B[K,N] (+bias) (+relu). 128x128 tile, BK=8,
// 256 threads, 8x8 per-thread tile. All dims divide tiles exactly.
// ---------------------------------------------------------------------------
template<int RELU>
__global__ __launch_bounds__(256)
void sgemm_k(const float* __restrict__ A, const float* __restrict__ B,
             const float* __restrict__ bias, float* __restrict__ C,
             int M, int N, int K)
{
    __shared__ float As[8][128];   // transposed: As[k][m]
    __shared__ float Bs[8][128];

    const int tid = threadIdx.x;
    const int bm  = blockIdx.y << 7;
    const int bn  = blockIdx.x << 7;
    const int tr  = (tid >> 4) << 3;    // 0..120
    const int tc  = (tid & 15) << 3;

    const int a_row = tid >> 1, a_col = (tid & 1) << 2;
    const int b_row = tid >> 5, b_col = (tid & 31) << 2;

    const float* Ag = A + (long)(bm + a_row) * K + a_col;
    const float* Bg = B + (long)b_row * N + bn + b_col;

    float4 av = *(const float4*)Ag;
    float4 bv = *(const float4*)Bg;

    float acc[8][8] = {};

    for (int k0 = 0; k0 < K; k0 += 8) {
        __syncthreads();
        As[a_col + 0][a_row] = av.x;
        As[a_col + 1][a_row] = av.y;
        As[a_col + 2][a_row] = av.z;
        As[a_col + 3][a_row] = av.w;
        *(float4*)&Bs[b_row][b_col] = bv;
        __syncthreads();

        if (k0 + 8 < K) {
            av = *(const float4*)(Ag + k0 + 8);
            bv = *(const float4*)(Bg + (long)(k0 + 8) * N);
        }

        #pragma unroll
        for (int kk = 0; kk < 8; kk++) {
            float4 a0 = *(const float4*)&As[kk][tr];
            float4 a1 = *(const float4*)&As[kk][tr + 4];
            float4 b0 = *(const float4*)&Bs[kk][tc];
            float4 b1 = *(const float4*)&Bs[kk][tc + 4];
            float a[8] = {a0.x,a0.y,a0.z,a0.w,a1.x,a1.y,a1.z,a1.w};
            float b[8] = {b0.x,b0.y,b0.z,b0.w,b1.x,b1.y,b1.z,b1.w};
            #pragma unroll
            for (int i = 0; i < 8; i++)
                #pragma unroll
                for (int j = 0; j < 8; j++)
                    acc[i][j] += a[i] * b[j];
        }
    }

    float bb[8];
    #pragma unroll
    for (int j = 0; j < 8; j++) bb[j] = bias ? bias[bn + tc + j] : 0.0f;

    #pragma unroll
    for (int i = 0; i < 8; i++) {
        float* crow = C + (long)(bm + tr + i) * N + bn + tc;
        float v[8];
        #pragma unroll
        for (int j = 0; j < 8; j++) {
            float c = acc[i][j] + bb[j];
            if (RELU) c = fmaxf(c, 0.0f);
            v[j] = c;
        }
        *(float4*)(crow)     = make_float4(v[0], v[1], v[2], v[3]);
        *(float4*)(crow + 4) = make_float4(v[4], v[5], v[6], v[7]);
    }
}

// ---------------------------------------------------------------------------
// Flash-style causal attention. Block = (b, h, 64-row q tile), 256 threads.
// Threads as 16x16 grid; each owns 4x4 of each 64x64 tile.
// qkv layout: [B*S, 3*D], Q at col h*64, K at 512+h*64, V at 1024+h*64.
// ---------------------------------------------------------------------------
#define ATT_PAD 68
#define ATT_SMEM (4 * 64 * ATT_PAD * (int)sizeof(float))   // 69632 B

__global__ __launch_bounds__(256)
void attn_k(const float* __restrict__ qkv, float* __restrict__ out)
{
    extern __shared__ float sm[];
    float* Qs = sm;
    float* Ks = sm + 64 * ATT_PAD;
    float* Vs = sm + 2 * 64 * ATT_PAD;
    float* Ps = sm + 3 * 64 * ATT_PAD;

    const int tid = threadIdx.x;
    const int qt = blockIdx.x, h = blockIdx.y, b = blockIdx.z;
    const int ty = tid >> 4, tx = tid & 15;
    const long rowbase = (long)b * SS;
    const int  qoff = h << 6;

    // load Q tile
    for (int i = tid; i < 1024; i += 256) {
        int r = i >> 4, c4 = (i & 15) << 2;
        float4 v = *(const float4*)(qkv + (rowbase + qt * 64 + r) * 1536 + qoff + c4);
        *(float4*)&Qs[r * ATT_PAD + c4] = v;
    }

    float m_i[4] = {-1e30f, -1e30f, -1e30f, -1e30f};
    float l_i[4] = {0, 0, 0, 0};
    float O[4][4] = {};

    for (int kt = 0; kt <= qt; kt++) {
        __syncthreads();
        for (int i = tid; i < 1024; i += 256) {
            int r = i >> 4, c4 = (i & 15) << 2;
            long gr = (rowbase + kt * 64 + r) * 1536 + qoff;
            *(float4*)&Ks[r * ATT_PAD + c4] = *(const float4*)(qkv + gr + 512 + c4);
            *(float4*)&Vs[r * ATT_PAD + c4] = *(const float4*)(qkv + gr + 1024 + c4);
        }
        __syncthreads();

        // S = Q K^T (4x4 per thread)
        float s[4][4] = {};
        const float* qb = Qs + ty * 4 * ATT_PAD;
        const float* kb = Ks + tx * 4 * ATT_PAD;
        #pragma unroll
        for (int d4 = 0; d4 < 16; d4++) {
            float4 qa[4], ka[4];
            #pragma unroll
            for (int i = 0; i < 4; i++) qa[i] = *(const float4*)(qb + i * ATT_PAD + d4 * 4);
            #pragma unroll
            for (int j = 0; j < 4; j++) ka[j] = *(const float4*)(kb + j * ATT_PAD + d4 * 4);
            #pragma unroll
            for (int i = 0; i < 4; i++)
                #pragma unroll
                for (int j = 0; j < 4; j++)
                    s[i][j] += qa[i].x*ka[j].x + qa[i].y*ka[j].y
                             + qa[i].z*ka[j].z + qa[i].w*ka[j].w;
        }

        const float scale = 0.125f;   // 1/sqrt(64)
        const bool diag = (kt == qt);
        #pragma unroll
        for (int i = 0; i < 4; i++) {
            int r = ty * 4 + i;
            float rm = -1e30f;
            #pragma unroll
            for (int j = 0; j < 4; j++) {
                float v = s[i][j] * scale;
                if (diag && (tx * 4 + j) > r) v = -1e30f;
                s[i][j] = v;
                rm = fmaxf(rm, v);
            }
            #pragma unroll
            for (int o = 8; o > 0; o >>= 1)
                rm = fmaxf(rm, __shfl_xor_sync(0xffffffffu, rm, o));
            float nm = fmaxf(m_i[i], rm);
            float sf = __expf(m_i[i] - nm);
            m_i[i] = nm;
            float rs = 0.f;
            #pragma unroll
            for (int j = 0; j < 4; j++) {
                float p = __expf(s[i][j] - nm);
                s[i][j] = p; rs += p;
            }
            #pragma unroll
            for (int o = 8; o > 0; o >>= 1)
                rs += __shfl_xor_sync(0xffffffffu, rs, o);
            l_i[i] = l_i[i] * sf + rs;
            #pragma unroll
            for (int j = 0; j < 4; j++) O[i][j] *= sf;
            *(float4*)&Ps[r * ATT_PAD + tx * 4] =
                make_float4(s[i][0], s[i][1], s[i][2], s[i][3]);
        }
        __syncthreads();

        // O += P V
        #pragma unroll
        for (int c4 = 0; c4 < 16; c4++) {
            float4 pv[4];
            #pragma unroll
            for (int i = 0; i < 4; i++)
                pv[i] = *(const float4*)&Ps[(ty * 4 + i) * ATT_PAD + c4 * 4];
            #pragma unroll
            for (int cc = 0; cc < 4; cc++) {
                float4 vv = *(const float4*)&Vs[(c4 * 4 + cc) * ATT_PAD + tx * 4];
                #pragma unroll
                for (int i = 0; i < 4; i++) {
                    float p = (cc == 0) ? pv[i].x : (cc == 1) ? pv[i].y
                            : (cc == 2) ? pv[i].z : pv[i].w;
                    O[i][0] += p * vv.x; O[i][1] += p * vv.y;
                    O[i][2] += p * vv.z; O[i][3] += p * vv.w;
                }
            }
        }
    }

    #pragma unroll
    for (int i = 0; i < 4; i++) {
        int r = ty * 4 + i;
        float inv = 1.0f / l_i[i];
        *(float4*)(out + (rowbase + qt * 64 + r) * DD + qoff + tx * 4) =
            make_float4(O[i][0]*inv, O[i][1]*inv, O[i][2]*inv, O[i][3]*inv);
    }
}

// ---------------------------------------------------------------------------
// out = LayerNorm(x (+ res)) * g + b   — one 128-thread block per 512-col row
// ---------------------------------------------------------------------------
__global__ void add_ln_k(const float* __restrict__ x, const float* __restrict__ res,
                         const float* __restrict__ g, const float* __restrict__ b,
                         float* __restrict__ out)
{
    int row = blockIdx.x, tid = threadIdx.x;
    float4 v = ((const float4*)(x + (long)row * DD))[tid];
    if (res) {
        float4 rv = ((const float4*)(res + (long)row * DD))[tid];
        v.x += rv.x; v.y += rv.y; v.z += rv.z; v.w += rv.w;
    }
    float s  = v.x + v.y + v.z + v.w;
    float s2 = v.x*v.x + v.y*v.y + v.z*v.z + v.w*v.w;
    #pragma unroll
    for (int o = 16; o; o >>= 1) {
        s  += __shfl_xor_sync(0xffffffffu, s,  o);
        s2 += __shfl_xor_sync(0xffffffffu, s2, o);
    }
    __shared__ float ssum[4], ssq[4];
    int wid = tid >> 5;
    if ((tid & 31) == 0) { ssum[wid] = s; ssq[wid] = s2; }
    __syncthreads();
    s  = ssum[0] + ssum[1] + ssum[2] + ssum[3];
    s2 = ssq[0]  + ssq[1]  + ssq[2]  + ssq[3];
    float mean = s * (1.0f / DD);
    float var  = s2 * (1.0f / DD) - mean * mean;
    float inv  = rsqrtf(var + 1e-5f);
    float4 gv = ((const float4*)g)[tid];
    float4 bv = ((const float4*)b)[tid];
    float4 o;
    o.x = (v.x - mean) * inv * gv.x + bv.x;
    o.y = (v.y - mean) * inv * gv.y + bv.y;
    o.z = (v.z - mean) * inv * gv.z + bv.z;
    o.w = (v.w - mean) * inv * gv.w + bv.w;
    ((float4*)(out + (long)row * DD))[tid] = o;
}

// ---------------------------------------------------------------------------
extern "C" void kernel_launch(void* const* d_in, const int* in_sizes, int n_in,
                              void* d_out, int out_size)
{
    const int*   x    = (const int*)  d_in[0];
    const float* emb  = (const float*)d_in[1];
    const float* pe   = (const float*)d_in[2];
    const float* Wqkv = (const float*)d_in[3];
    const float* Wo   = (const float*)d_in[4];
    const float* bo   = (const float*)d_in[5];
    const float* g1   = (const float*)d_in[6];
    const float* b1   = (const float*)d_in[7];
    const float* g2   = (const float*)d_in[8];
    const float* b2   = (const float*)d_in[9];
    const float* W1   = (const float*)d_in[10];
    const float* bf1  = (const float*)d_in[11];
    const float* W2   = (const float*)d_in[12];
    const float* bf2  = (const float*)d_in[13];
    const float* gf   = (const float*)d_in[14];
    const float* bfp  = (const float*)d_in[15];
    const float* Wout = (const float*)d_in[16];
    const float* bfc  = (const float*)d_in[17];
    float* out = (float*)d_out;

    float *h, *big, *o, *t;
    cudaGetSymbolAddress((void**)&h,   g_h);
    cudaGetSymbolAddress((void**)&big, g_big);
    cudaGetSymbolAddress((void**)&o,   g_o);
    cudaGetSymbolAddress((void**)&t,   g_t);

    cudaFuncSetAttribute(attn_k, cudaFuncAttributeMaxDynamicSharedMemorySize, ATT_SMEM);

    embed_k<<<ROWS, 128>>>(x, emb, pe, h);

    for (int l = 0; l < LL; l++) {
        // QKV projection: [4096,512] @ [512,1536]
        sgemm_k<0><<<dim3(12, 32), 256>>>(h, Wqkv + (long)l * DD * 3 * DD,
                                          nullptr, big, ROWS, 3 * DD, DD);
        // causal attention
        attn_k<<<dim3(SS / 64, HH, BB), 256, ATT_SMEM>>>(big, o);
        // output projection + bias
        sgemm_k<0><<<dim3(4, 32), 256>>>(o, Wo + (long)l * DD * DD,
                                         bo + l * DD, t, ROWS, DD, DD);
        // h = LN(h + attn_out)
        add_ln_k<<<ROWS, 128>>>(t, h, g1 + l * DD, b1 + l * DD, h);
        // FF1 + relu
        sgemm_k<1><<<dim3(16, 32), 256>>>(h, W1 + (long)l * DD * FF,
                                          bf1 + l * FF, big, ROWS, FF, DD);
        // FF2
        sgemm_k<0><<<dim3(4, 32), 256>>>(big, W2 + (long)l * FF * DD,
                                         bf2 + l * DD, t, ROWS, DD, FF);
        // h = LN(h + ff)
        add_ln_k<<<ROWS, 128>>>(t, h, g2 + l * DD, b2 + l * DD, h);
    }

    // final LN (no residual)
    add_ln_k<<<ROWS, 128>>>(h, nullptr, gf, bfp, t);
    // logits: [4096,512] @ [512,32000] + bfc
    sgemm_k<0><<<dim3(VV / 128, 32), 256>>>(t, Wout, bfc, out, ROWS, VV, DD);
}

// round 2
// speedup vs baseline: 1.1626x; 1.1626x over previous
#include <cuda_runtime.h>
#include <cuda_bf16.h>
#include <cstdint>

// Model dims
#define BB 2
#define SS 2048
#define DD 512
#define LL 6
#define HH 8
#define FF 2048
#define VV 32000
#define ROWS (BB*SS)   // 4096

// Scratch (device globals: no allocations allowed)
__device__ float g_h  [ROWS * DD];
__device__ float g_big[ROWS * FF];
__device__ float g_o  [ROWS * DD];
__device__ float g_t  [ROWS * DD];

// ---------------------------------------------------------------------------
// Embedding + positional encoding
// ---------------------------------------------------------------------------
__global__ void embed_k(const int* __restrict__ x, const float* __restrict__ emb,
                        const float* __restrict__ pe, float* __restrict__ h)
{
    int row = blockIdx.x;
    int s   = row & (SS - 1);
    int tok = x[row];
    const float4* e = (const float4*)(emb + (long)tok * DD);
    const float4* p = (const float4*)(pe  + (long)s   * DD);
    float4 ev = e[threadIdx.x], pv = p[threadIdx.x];
    float4 o;
    o.x = ev.x + pv.x; o.y = ev.y + pv.y; o.z = ev.z + pv.z; o.w = ev.w + pv.w;
    ((float4*)(h + (long)row * DD))[threadIdx.x] = o;
}

// ---------------------------------------------------------------------------
// 3xTF32 tensor-core GEMM: C[M,N] = A[M,K] @ B[K,N] (+bias) (+relu)
// Block tile 128x128, BK=32, 8 warps (warp tile 64x32), mma.m16n8k8.tf32,
// cp.async double-buffered smem, conflict-free fragment strides.
// ---------------------------------------------------------------------------
#define BM 128
#define BN 128
#define BKK 32
#define ASTR 36      // smem A row stride (floats): bank = 4g+c, conflict-free
#define BSTR 136     // smem B row stride (floats): bank = 8c+g, conflict-free
#define A_TILE (BM*ASTR)   // floats
#define B_TILE (BKK*BSTR)
#define GEMM_SMEM ((2*A_TILE + 2*B_TILE)*(int)sizeof(float))  // 71680 B

__device__ __forceinline__ void cpa16(uint32_t s, const float* g) {
    asm volatile("cp.async.cg.shared.global [%0], [%1], 16;" :: "r"(s), "l"(g));
}
__device__ __forceinline__ void tf32_split(float x, uint32_t& hi, uint32_t& lo) {
    asm("cvt.rna.tf32.f32 %0, %1;" : "=r"(hi) : "f"(x));
    float l = x - __uint_as_float(hi);
    asm("cvt.rna.tf32.f32 %0, %1;" : "=r"(lo) : "f"(l));
}
__device__ __forceinline__ void mma8(float* d, const uint32_t* a, const uint32_t* b) {
    asm volatile("mma.sync.aligned.m16n8k8.row.col.f32.tf32.tf32.f32 "
        "{%0,%1,%2,%3}, {%4,%5,%6,%7}, {%8,%9}, {%0,%1,%2,%3};"
        : "+f"(d[0]), "+f"(d[1]), "+f"(d[2]), "+f"(d[3])
        : "r"(a[0]), "r"(a[1]), "r"(a[2]), "r"(a[3]), "r"(b[0]), "r"(b[1]));
}

template<int RELU>
__global__ __launch_bounds__(256)
void tf32_gemm_k(const float* __restrict__ A, const float* __restrict__ B,
                 const float* __restrict__ bias, float* __restrict__ C,
                 int M, int N, int K)
{
    extern __shared__ float sm[];
    float* As = sm;                 // 2 x A_TILE
    float* Bs = sm + 2 * A_TILE;    // 2 x B_TILE

    const int tid  = threadIdx.x;
    const int bm   = blockIdx.y * BM;
    const int bn   = blockIdx.x * BN;
    const int warp = tid >> 5, lane = tid & 31;
    const int wm   = (warp >> 2) * 64;   // 2 warp rows
    const int wn   = (warp & 3) * 32;    // 4 warp cols
    const int g    = lane >> 2, c = lane & 3;

    // global->smem staging assignments
    const int am = tid >> 1;             // A row 0..127
    const int ak = (tid & 1) * 16;       // 16 floats per thread
    const float* Ag = A + (long)(bm + am) * K + ak;
    const int a_s = am * ASTR + ak;

    const int br = tid >> 3;             // B row 0..31
    const int bc = (tid & 7) * 16;       // 16 floats per thread
    const float* Bg = B + (long)br * N + bn + bc;
    const int b_s = br * BSTR + bc;

    const uint32_t smem_a = (uint32_t)__cvta_generic_to_shared(As);
    const uint32_t smem_b = (uint32_t)__cvta_generic_to_shared(Bs);

    float acc[4][4][4] = {};   // [mt][nt][4]

    const int T = K / BKK;

    // prefetch tile 0 into buf 0
    {
        #pragma unroll
        for (int i = 0; i < 4; i++) cpa16(smem_a + (a_s + i*4)*4, Ag + i*4);
        #pragma unroll
        for (int i = 0; i < 4; i++) cpa16(smem_b + (b_s + i*4)*4, Bg + i*4);
        asm volatile("cp.async.commit_group;");
    }

    for (int t = 0; t < T; t++) {
        __syncthreads();   // everyone done with buf[(t+1)&1] contents from t-1
        if (t + 1 < T) {
            const float* ag = Ag + (t + 1) * BKK;
            const float* bg = Bg + (long)(t + 1) * BKK * N;
            const int abuf = ((t + 1) & 1) * A_TILE;
            const int bbuf = ((t + 1) & 1) * B_TILE;
            #pragma unroll
            for (int i = 0; i < 4; i++) cpa16(smem_a + (abuf + a_s + i*4)*4, ag + i*4);
            #pragma unroll
            for (int i = 0; i < 4; i++) cpa16(smem_b + (bbuf + b_s + i*4)*4, bg + i*4);
            asm volatile("cp.async.commit_group;");
            asm volatile("cp.async.wait_group 1;");
        } else {
            asm volatile("cp.async.wait_group 0;");
        }
        __syncthreads();   // tile t visible

        const float* Ab = As + (t & 1) * A_TILE;
        const float* Bb = Bs + (t & 1) * B_TILE;

        #pragma unroll
        for (int kk = 0; kk < 4; kk++) {
            uint32_t Ah[4][4], Al[4][4];
            #pragma unroll
            for (int mt = 0; mt < 4; mt++) {
                const float* p = Ab + (wm + mt*16 + g) * ASTR + kk*8 + c;
                float a0 = p[0];
                float a2 = p[4];
                float a1 = p[8 * ASTR];
                float a3 = p[8 * ASTR + 4];
                tf32_split(a0, Ah[mt][0], Al[mt][0]);
                tf32_split(a1, Ah[mt][1], Al[mt][1]);
                tf32_split(a2, Ah[mt][2], Al[mt][2]);
                tf32_split(a3, Ah[mt][3], Al[mt][3]);
            }
            uint32_t Bh[4][2], Bl[4][2];
            #pragma unroll
            for (int nt = 0; nt < 4; nt++) {
                const float* p = Bb + (kk*8 + c) * BSTR + wn + nt*8 + g;
                float b0 = p[0];
                float b1 = p[4 * BSTR];
                tf32_split(b0, Bh[nt][0], Bl[nt][0]);
                tf32_split(b1, Bh[nt][1], Bl[nt][1]);
            }
            #pragma unroll
            for (int mt = 0; mt < 4; mt++)
                #pragma unroll
                for (int nt = 0; nt < 4; nt++) {
                    mma8(acc[mt][nt], Ah[mt], Bh[nt]);
                    mma8(acc[mt][nt], Ah[mt], Bl[nt]);
                    mma8(acc[mt][nt], Al[mt], Bh[nt]);
                }
        }
    }

    // epilogue: bias (+relu), write float2 pairs
    #pragma unroll
    for (int mt = 0; mt < 4; mt++) {
        #pragma unroll
        for (int nt = 0; nt < 4; nt++) {
            int col = bn + wn + nt*8 + c*2;
            float2 bv = make_float2(0.f, 0.f);
            if (bias) bv = *(const float2*)(bias + col);
            int r0 = bm + wm + mt*16 + g;
            float2 v0 = make_float2(acc[mt][nt][0] + bv.x, acc[mt][nt][1] + bv.y);
            float2 v1 = make_float2(acc[mt][nt][2] + bv.x, acc[mt][nt][3] + bv.y);
            if (RELU) {
                v0.x = fmaxf(v0.x, 0.f); v0.y = fmaxf(v0.y, 0.f);
                v1.x = fmaxf(v1.x, 0.f); v1.y = fmaxf(v1.y, 0.f);
            }
            *(float2*)(C + (long)r0 * N + col)       = v0;
            *(float2*)(C + (long)(r0 + 8) * N + col) = v1;
        }
    }
}

// ---------------------------------------------------------------------------
// Flash-style causal attention (unchanged from round 1)
// ---------------------------------------------------------------------------
#define ATT_PAD 68
#define ATT_SMEM (4 * 64 * ATT_PAD * (int)sizeof(float))

__global__ __launch_bounds__(256)
void attn_k(const float* __restrict__ qkv, float* __restrict__ out)
{
    extern __shared__ float sm[];
    float* Qs = sm;
    float* Ks = sm + 64 * ATT_PAD;
    float* Vs = sm + 2 * 64 * ATT_PAD;
    float* Ps = sm + 3 * 64 * ATT_PAD;

    const int tid = threadIdx.x;
    const int qt = blockIdx.x, h = blockIdx.y, b = blockIdx.z;
    const int ty = tid >> 4, tx = tid & 15;
    const long rowbase = (long)b * SS;
    const int  qoff = h << 6;

    for (int i = tid; i < 1024; i += 256) {
        int r = i >> 4, c4 = (i & 15) << 2;
        float4 v = *(const float4*)(qkv + (rowbase + qt * 64 + r) * 1536 + qoff + c4);
        *(float4*)&Qs[r * ATT_PAD + c4] = v;
    }

    float m_i[4] = {-1e30f, -1e30f, -1e30f, -1e30f};
    float l_i[4] = {0, 0, 0, 0};
    float O[4][4] = {};

    for (int kt = 0; kt <= qt; kt++) {
        __syncthreads();
        for (int i = tid; i < 1024; i += 256) {
            int r = i >> 4, c4 = (i & 15) << 2;
            long gr = (rowbase + kt * 64 + r) * 1536 + qoff;
            *(float4*)&Ks[r * ATT_PAD + c4] = *(const float4*)(qkv + gr + 512 + c4);
            *(float4*)&Vs[r * ATT_PAD + c4] = *(const float4*)(qkv + gr + 1024 + c4);
        }
        __syncthreads();

        float s[4][4] = {};
        const float* qb = Qs + ty * 4 * ATT_PAD;
        const float* kb = Ks + tx * 4 * ATT_PAD;
        #pragma unroll
        for (int d4 = 0; d4 < 16; d4++) {
            float4 qa[4], ka[4];
            #pragma unroll
            for (int i = 0; i < 4; i++) qa[i] = *(const float4*)(qb + i * ATT_PAD + d4 * 4);
            #pragma unroll
            for (int j = 0; j < 4; j++) ka[j] = *(const float4*)(kb + j * ATT_PAD + d4 * 4);
            #pragma unroll
            for (int i = 0; i < 4; i++)
                #pragma unroll
                for (int j = 0; j < 4; j++)
                    s[i][j] += qa[i].x*ka[j].x + qa[i].y*ka[j].y
                             + qa[i].z*ka[j].z + qa[i].w*ka[j].w;
        }

        const float scale = 0.125f;
        const bool diag = (kt == qt);
        #pragma unroll
        for (int i = 0; i < 4; i++) {
            int r = ty * 4 + i;
            float rm = -1e30f;
            #pragma unroll
            for (int j = 0; j < 4; j++) {
                float v = s[i][j] * scale;
                if (diag && (tx * 4 + j) > r) v = -1e30f;
                s[i][j] = v;
                rm = fmaxf(rm, v);
            }
            #pragma unroll
            for (int o = 8; o > 0; o >>= 1)
                rm = fmaxf(rm, __shfl_xor_sync(0xffffffffu, rm, o));
            float nm = fmaxf(m_i[i], rm);
            float sf = __expf(m_i[i] - nm);
            m_i[i] = nm;
            float rs = 0.f;
            #pragma unroll
            for (int j = 0; j < 4; j++) {
                float p = __expf(s[i][j] - nm);
                s[i][j] = p; rs += p;
            }
            #pragma unroll
            for (int o = 8; o > 0; o >>= 1)
                rs += __shfl_xor_sync(0xffffffffu, rs, o);
            l_i[i] = l_i[i] * sf + rs;
            #pragma unroll
            for (int j = 0; j < 4; j++) O[i][j] *= sf;
            *(float4*)&Ps[r * ATT_PAD + tx * 4] =
                make_float4(s[i][0], s[i][1], s[i][2], s[i][3]);
        }
        __syncthreads();

        #pragma unroll
        for (int c4 = 0; c4 < 16; c4++) {
            float4 pv[4];
            #pragma unroll
            for (int i = 0; i < 4; i++)
                pv[i] = *(const float4*)&Ps[(ty * 4 + i) * ATT_PAD + c4 * 4];
            #pragma unroll
            for (int cc = 0; cc < 4; cc++) {
                float4 vv = *(const float4*)&Vs[(c4 * 4 + cc) * ATT_PAD + tx * 4];
                #pragma unroll
                for (int i = 0; i < 4; i++) {
                    float p = (cc == 0) ? pv[i].x : (cc == 1) ? pv[i].y
                            : (cc == 2) ? pv[i].z : pv[i].w;
                    O[i][0] += p * vv.x; O[i][1] += p * vv.y;
                    O[i][2] += p * vv.z; O[i][3] += p * vv.w;
                }
            }
        }
    }

    #pragma unroll
    for (int i = 0; i < 4; i++) {
        int r = ty * 4 + i;
        float inv = 1.0f / l_i[i];
        *(float4*)(out + (rowbase + qt * 64 + r) * DD + qoff + tx * 4) =
            make_float4(O[i][0]*inv, O[i][1]*inv, O[i][2]*inv, O[i][3]*inv);
    }
}

// ---------------------------------------------------------------------------
// out = LayerNorm(x (+ res)) * g + b
// ---------------------------------------------------------------------------
__global__ void add_ln_k(const float* __restrict__ x, const float* __restrict__ res,
                         const float* __restrict__ g, const float* __restrict__ b,
                         float* __restrict__ out)
{
    int row = blockIdx.x, tid = threadIdx.x;
    float4 v = ((const float4*)(x + (long)row * DD))[tid];
    if (res) {
        float4 rv = ((const float4*)(res + (long)row * DD))[tid];
        v.x += rv.x; v.y += rv.y; v.z += rv.z; v.w += rv.w;
    }
    float s  = v.x + v.y + v.z + v.w;
    float s2 = v.x*v.x + v.y*v.y + v.z*v.z + v.w*v.w;
    #pragma unroll
    for (int o = 16; o; o >>= 1) {
        s  += __shfl_xor_sync(0xffffffffu, s,  o);
        s2 += __shfl_xor_sync(0xffffffffu, s2, o);
    }
    __shared__ float ssum[4], ssq[4];
    int wid = tid >> 5;
    if ((tid & 31) == 0) { ssum[wid] = s; ssq[wid] = s2; }
    __syncthreads();
    s  = ssum[0] + ssum[1] + ssum[2] + ssum[3];
    s2 = ssq[0]  + ssq[1]  + ssq[2]  + ssq[3];
    float mean = s * (1.0f / DD);
    float var  = s2 * (1.0f / DD) - mean * mean;
    float inv  = rsqrtf(var + 1e-5f);
    float4 gv = ((const float4*)g)[tid];
    float4 bv = ((const float4*)b)[tid];
    float4 o;
    o.x = (v.x - mean) * inv * gv.x + bv.x;
    o.y = (v.y - mean) * inv * gv.y + bv.y;
    o.z = (v.z - mean) * inv * gv.z + bv.z;
    o.w = (v.w - mean) * inv * gv.w + bv.w;
    ((float4*)(out + (long)row * DD))[tid] = o;
}

// ---------------------------------------------------------------------------
extern "C" void kernel_launch(void* const* d_in, const int* in_sizes, int n_in,
                              void* d_out, int out_size)
{
    const int*   x    = (const int*)  d_in[0];
    const float* emb  = (const float*)d_in[1];
    const float* pe   = (const float*)d_in[2];
    const float* Wqkv = (const float*)d_in[3];
    const float* Wo   = (const float*)d_in[4];
    const float* bo   = (const float*)d_in[5];
    const float* g1   = (const float*)d_in[6];
    const float* b1   = (const float*)d_in[7];
    const float* g2   = (const float*)d_in[8];
    const float* b2   = (const float*)d_in[9];
    const float* W1   = (const float*)d_in[10];
    const float* bf1  = (const float*)d_in[11];
    const float* W2   = (const float*)d_in[12];
    const float* bf2  = (const float*)d_in[13];
    const float* gf   = (const float*)d_in[14];
    const float* bfp  = (const float*)d_in[15];
    const float* Wout = (const float*)d_in[16];
    const float* bfc  = (const float*)d_in[17];
    float* out = (float*)d_out;

    float *h, *big, *o, *t;
    cudaGetSymbolAddress((void**)&h,   g_h);
    cudaGetSymbolAddress((void**)&big, g_big);
    cudaGetSymbolAddress((void**)&o,   g_o);
    cudaGetSymbolAddress((void**)&t,   g_t);

    cudaFuncSetAttribute(attn_k, cudaFuncAttributeMaxDynamicSharedMemorySize, ATT_SMEM);
    cudaFuncSetAttribute(tf32_gemm_k<0>, cudaFuncAttributeMaxDynamicSharedMemorySize, GEMM_SMEM);
    cudaFuncSetAttribute(tf32_gemm_k<1>, cudaFuncAttributeMaxDynamicSharedMemorySize, GEMM_SMEM);

    embed_k<<<ROWS, 128>>>(x, emb, pe, h);

    for (int l = 0; l < LL; l++) {
        // QKV projection: [4096,512] @ [512,1536]
        tf32_gemm_k<0><<<dim3(12, 32), 256, GEMM_SMEM>>>(
            h, Wqkv + (long)l * DD * 3 * DD, nullptr, big, ROWS, 3 * DD, DD);
        // causal attention
        attn_k<<<dim3(SS / 64, HH, BB), 256, ATT_SMEM>>>(big, o);
        // output projection + bias
        tf32_gemm_k<0><<<dim3(4, 32), 256, GEMM_SMEM>>>(
            o, Wo + (long)l * DD * DD, bo + l * DD, t, ROWS, DD, DD);
        // h = LN(h + attn_out)
        add_ln_k<<<ROWS, 128>>>(t, h, g1 + l * DD, b1 + l * DD, h);
        // FF1 + relu
        tf32_gemm_k<1><<<dim3(16, 32), 256, GEMM_SMEM>>>(
            h, W1 + (long)l * DD * FF, bf1 + l * FF, big, ROWS, FF, DD);
        // FF2
        tf32_gemm_k<0><<<dim3(4, 32), 256, GEMM_SMEM>>>(
            big, W2 + (long)l * FF * DD, bf2 + l * DD, t, ROWS, DD, FF);
        // h = LN(h + ff)
        add_ln_k<<<ROWS, 128>>>(t, h, g2 + l * DD, b2 + l * DD, h);
    }

    add_ln_k<<<ROWS, 128>>>(h, nullptr, gf, bfp, t);
    tf32_gemm_k<0><<<dim3(VV / 128, 32), 256, GEMM_SMEM>>>(
        t, Wout, bfc, out, ROWS, VV, DD);
}

// round 6
// speedup vs baseline: 1.6405x; 1.4110x over previous
#include <cuda_runtime.h>
#include <cuda_bf16.h>
#include <cstdint>

#define BB 2
#define SS 2048
#define DD 512
#define LL 6
#define HH 8
#define FF 2048
#define VV 32000
#define ROWS (BB*SS)   // 4096

// fp32 residual stream scratch
__device__ float g_h  [ROWS * DD];
__device__ float g_big[ROWS * FF];   // qkv output fp32 (for attention)
__device__ float g_t  [ROWS * DD];
// packed bf16 hi/lo activation planes
__device__ __align__(16) __nv_bfloat16 g_hh [ROWS * DD],  g_hl [ROWS * DD];
__device__ __align__(16) __nv_bfloat16 g_oh [ROWS * DD],  g_ol [ROWS * DD];
__device__ __align__(16) __nv_bfloat16 g_fh [ROWS * FF],  g_fl [ROWS * FF];
__device__ __align__(16) __nv_bfloat16 g_th [ROWS * DD],  g_tl [ROWS * DD];
// pre-transposed bf16-split weights: [N][K] row-major
__device__ __align__(16) __nv_bfloat16 g_qkvT_h[LL * 3*DD * DD], g_qkvT_l[LL * 3*DD * DD];
__device__ __align__(16) __nv_bfloat16 g_woT_h [LL * DD * DD],   g_woT_l [LL * DD * DD];
__device__ __align__(16) __nv_bfloat16 g_w1T_h [LL * FF * DD],   g_w1T_l [LL * FF * DD];
__device__ __align__(16) __nv_bfloat16 g_w2T_h [LL * DD * FF],   g_w2T_l [LL * DD * FF];
__device__ __align__(16) __nv_bfloat16 g_outT_h[VV * DD],        g_outT_l[VV * DD];

// single dynamic smem symbol shared by all kernels
extern __shared__ char dynsm[];

// ---------------------------------------------------------------------------
__device__ __forceinline__ uint32_t smem_u32(const void* p) {
    uint32_t a;
    asm("{ .reg .u64 t; cvta.to.shared.u64 t, %1; cvt.u32.u64 %0, t; }"
        : "=r"(a) : "l"(p));
    return a;
}
__device__ __forceinline__ void cpa16(uint32_t s, const void* g) {
    asm volatile("cp.async.cg.shared.global [%0], [%1], 16;" :: "r"(s), "l"(g));
}
__device__ __forceinline__ void split2(float x0, float x1, uint32_t& hw, uint32_t& lw) {
    __nv_bfloat16 h0 = __float2bfloat16(x0), h1 = __float2bfloat16(x1);
    __nv_bfloat16 l0 = __float2bfloat16(x0 - __bfloat162float(h0));
    __nv_bfloat16 l1 = __float2bfloat16(x1 - __bfloat162float(h1));
    __nv_bfloat162 hp(h0, h1), lp(l0, l1);
    hw = *(uint32_t*)&hp;
    lw = *(uint32_t*)&lp;
}
__device__ __forceinline__ void mma_bf16(float* d, const uint32_t* a, const uint32_t* b) {
    asm volatile("mma.sync.aligned.m16n8k16.row.col.f32.bf16.bf16.f32 "
        "{%0,%1,%2,%3}, {%4,%5,%6,%7}, {%8,%9}, {%0,%1,%2,%3};"
        : "+f"(d[0]), "+f"(d[1]), "+f"(d[2]), "+f"(d[3])
        : "r"(a[0]), "r"(a[1]), "r"(a[2]), "r"(a[3]), "r"(b[0]), "r"(b[1]));
}

// ---------------------------------------------------------------------------
// Weight prep: W[K,N] fp32 -> WT hi/lo [N,K] bf16 (transpose + split)
// ---------------------------------------------------------------------------
__global__ void wprep_k(const float* __restrict__ W, __nv_bfloat16* __restrict__ hi,
                        __nv_bfloat16* __restrict__ lo, int K, int N)
{
    __shared__ float ts[32][33];
    long moff = (long)blockIdx.z * K * N;
    int kb = blockIdx.y * 32, nb = blockIdx.x * 32;
    int r = threadIdx.x >> 5, c = threadIdx.x & 31;
    #pragma unroll
    for (int i = 0; i < 4; i++)
        ts[r + i*8][c] = W[moff + (long)(kb + r + i*8) * N + nb + c];
    __syncthreads();
    #pragma unroll
    for (int i = 0; i < 4; i++) {
        int n = r + i*8;
        float x = ts[c][n];
        __nv_bfloat16 h = __float2bfloat16(x);
        __nv_bfloat16 l = __float2bfloat16(x - __bfloat162float(h));
        long oidx = moff + (long)(nb + n) * K + kb + c;
        hi[oidx] = h;
        lo[oidx] = l;
    }
}

// ---------------------------------------------------------------------------
// Embedding + PE -> fp32 h + packed hi/lo planes
// ---------------------------------------------------------------------------
__global__ void embed_k(const int* __restrict__ x, const float* __restrict__ emb,
                        const float* __restrict__ pe, float* __restrict__ h,
                        uint32_t* __restrict__ oh, uint32_t* __restrict__ ol)
{
    int row = blockIdx.x, tid = threadIdx.x;
    int s   = row & (SS - 1);
    int tok = x[row];
    float4 ev = ((const float4*)(emb + (long)tok * DD))[tid];
    float4 pv = ((const float4*)(pe  + (long)s   * DD))[tid];
    float4 o;
    o.x = ev.x + pv.x; o.y = ev.y + pv.y; o.z = ev.z + pv.z; o.w = ev.w + pv.w;
    ((float4*)(h + (long)row * DD))[tid] = o;
    uint32_t hw, lw;
    int wi = row * (DD/2) + tid * 2;
    split2(o.x, o.y, hw, lw); oh[wi] = hw;   ol[wi] = lw;
    split2(o.z, o.w, hw, lw); oh[wi+1] = hw; ol[wi+1] = lw;
}

// ---------------------------------------------------------------------------
// out = LayerNorm(x (+ res)) * g + b -> fp32 + hi/lo planes
// ---------------------------------------------------------------------------
__global__ void add_ln_k(const float* __restrict__ x, const float* __restrict__ res,
                         const float* __restrict__ gg, const float* __restrict__ bb,
                         float* __restrict__ outF,
                         uint32_t* __restrict__ outH, uint32_t* __restrict__ outL)
{
    int row = blockIdx.x, tid = threadIdx.x;
    float4 v = ((const float4*)(x + (long)row * DD))[tid];
    if (res) {
        float4 rv = ((const float4*)(res + (long)row * DD))[tid];
        v.x += rv.x; v.y += rv.y; v.z += rv.z; v.w += rv.w;
    }
    float s  = v.x + v.y + v.z + v.w;
    float s2 = v.x*v.x + v.y*v.y + v.z*v.z + v.w*v.w;
    #pragma unroll
    for (int o = 16; o; o >>= 1) {
        s  += __shfl_xor_sync(0xffffffffu, s,  o);
        s2 += __shfl_xor_sync(0xffffffffu, s2, o);
    }
    __shared__ float ssum[4], ssq[4];
    int wid = tid >> 5;
    if ((tid & 31) == 0) { ssum[wid] = s; ssq[wid] = s2; }
    __syncthreads();
    s  = ssum[0] + ssum[1] + ssum[2] + ssum[3];
    s2 = ssq[0]  + ssq[1]  + ssq[2]  + ssq[3];
    float mean = s * (1.0f / DD);
    float var  = s2 * (1.0f / DD) - mean * mean;
    float inv  = rsqrtf(var + 1e-5f);
    float4 gv = ((const float4*)gg)[tid];
    float4 bv = ((const float4*)bb)[tid];
    float4 o;
    o.x = (v.x - mean) * inv * gv.x + bv.x;
    o.y = (v.y - mean) * inv * gv.y + bv.y;
    o.z = (v.z - mean) * inv * gv.z + bv.z;
    o.w = (v.w - mean) * inv * gv.w + bv.w;
    ((float4*)(outF + (long)row * DD))[tid] = o;
    uint32_t hw, lw;
    int wi = row * (DD/2) + tid * 2;
    split2(o.x, o.y, hw, lw); outH[wi] = hw;   outL[wi] = lw;
    split2(o.z, o.w, hw, lw); outH[wi+1] = hw; outL[wi+1] = lw;
}

// ---------------------------------------------------------------------------
// bf16 3-term tensor GEMM: C[M,N] = A[M,K] @ BT[N,K] (+bias)(+relu)
// A,B as packed bf16 hi/lo planes. 128x128x32 tiles, 8 warps (64x32 each),
// mma m16n8k16, cp.async double-buffered, stride-20-word smem.
// OUTMODE 0: fp32 C.  OUTMODE 1: packed hi/lo planes.
// ---------------------------------------------------------------------------
#define GSTR 20
#define GPL  (128*GSTR)            // words per plane  (10240 B)
#define GEMM_SMEM (8*GPL*4)        // 2 bufs x 4 planes = 81920 B

template<int RELU, int OUTMODE>
__global__ __launch_bounds__(256)
void gemm_bf16(const __nv_bfloat16* __restrict__ Ahp, const __nv_bfloat16* __restrict__ Alp,
               const __nv_bfloat16* __restrict__ Bhp, const __nv_bfloat16* __restrict__ Blp,
               const float* __restrict__ bias,
               float* __restrict__ C, uint32_t* __restrict__ Chw, uint32_t* __restrict__ Clw,
               int M, int N, int K)
{
    uint32_t* sm = (uint32_t*)dynsm;
    const int tid = threadIdx.x, warp = tid >> 5, lane = tid & 31;
    const int g = lane >> 2, c = lane & 3;
    const int bm = blockIdx.x * 128, bn = blockIdx.y * 128;
    const int wm = (warp >> 2) * 64, wn = (warp & 3) * 32;
    const uint32_t sb = smem_u32(sm);
    const int T = K / 32;

    auto stage = [&](int t, int b) {
        #pragma unroll
        for (int i = 0; i < 2; i++) {
            int id = tid + 256 * i, row = id >> 2, cc = id & 3;
            uint32_t doff = (uint32_t)(row * GSTR + cc * 4) * 4;
            uint32_t dbase = sb + (uint32_t)(b * 4 * GPL) * 4 + doff;
            long asrc = (long)(bm + row) * K + t * 32 + cc * 8;
            long bsrc = (long)(bn + row) * K + t * 32 + cc * 8;
            cpa16(dbase,             Ahp + asrc);
            cpa16(dbase + GPL*4,     Alp + asrc);
            cpa16(dbase + 2*GPL*4,   Bhp + bsrc);
            cpa16(dbase + 3*GPL*4,   Blp + bsrc);
        }
        asm volatile("cp.async.commit_group;");
    };

    float acc[4][4][4] = {};

    stage(0, 0);
    if (T > 1) stage(1, 1);

    for (int t = 0; t < T; t++) {
        if (t + 1 < T) asm volatile("cp.async.wait_group 1;");
        else           asm volatile("cp.async.wait_group 0;");
        __syncthreads();

        const uint32_t* Ahs = sm + (t & 1) * 4 * GPL;
        const uint32_t* Als = Ahs + GPL;
        const uint32_t* Bhs = Ahs + 2 * GPL;
        const uint32_t* Bls = Ahs + 3 * GPL;

        #pragma unroll
        for (int kk = 0; kk < 2; kk++) {
            uint32_t ah[4][4], al[4][4];
            #pragma unroll
            for (int mt = 0; mt < 4; mt++) {
                int ar = (wm + mt*16 + g) * GSTR + kk*8 + c;
                ah[mt][0] = Ahs[ar];     ah[mt][1] = Ahs[ar + 8*GSTR];
                ah[mt][2] = Ahs[ar + 4]; ah[mt][3] = Ahs[ar + 8*GSTR + 4];
                al[mt][0] = Als[ar];     al[mt][1] = Als[ar + 8*GSTR];
                al[mt][2] = Als[ar + 4]; al[mt][3] = Als[ar + 8*GSTR + 4];
            }
            #pragma unroll
            for (int nt = 0; nt < 4; nt++) {
                int br = (wn + nt*8 + g) * GSTR + kk*8 + c;
                uint32_t bh[2] = {Bhs[br], Bhs[br + 4]};
                uint32_t bl[2] = {Bls[br], Bls[br + 4]};
                #pragma unroll
                for (int mt = 0; mt < 4; mt++) {
                    mma_bf16(acc[mt][nt], ah[mt], bh);
                    mma_bf16(acc[mt][nt], ah[mt], bl);
                    mma_bf16(acc[mt][nt], al[mt], bh);
                }
            }
        }
        __syncthreads();
        if (t + 2 < T) stage(t + 2, t & 1);
    }

    #pragma unroll
    for (int mt = 0; mt < 4; mt++) {
        #pragma unroll
        for (int nt = 0; nt < 4; nt++) {
            int col = bn + wn + nt*8 + 2*c;
            float bx = 0.f, by = 0.f;
            if (bias) { bx = bias[col]; by = bias[col + 1]; }
            long r0 = bm + wm + mt*16 + g;
            float v0 = acc[mt][nt][0] + bx, v1 = acc[mt][nt][1] + by;
            float v2 = acc[mt][nt][2] + bx, v3 = acc[mt][nt][3] + by;
            if (RELU) {
                v0 = fmaxf(v0, 0.f); v1 = fmaxf(v1, 0.f);
                v2 = fmaxf(v2, 0.f); v3 = fmaxf(v3, 0.f);
            }
            if (OUTMODE == 0) {
                *(float2*)(C + r0 * N + col)       = make_float2(v0, v1);
                *(float2*)(C + (r0 + 8) * N + col) = make_float2(v2, v3);
            } else {
                uint32_t hw, lw;
                split2(v0, v1, hw, lw);
                Chw[(r0 * N + col) >> 1] = hw; Clw[(r0 * N + col) >> 1] = lw;
                split2(v2, v3, hw, lw);
                Chw[((r0 + 8) * N + col) >> 1] = hw; Clw[((r0 + 8) * N + col) >> 1] = lw;
            }
        }
    }
}

// ---------------------------------------------------------------------------
// Flash-style causal attention (SIMT, known-good); epilogue emits hi/lo planes
// ---------------------------------------------------------------------------
#define ATT_PAD 68
#define ATT_SMEM (4 * 64 * ATT_PAD * (int)sizeof(float))

__global__ __launch_bounds__(256)
void attn_k(const float* __restrict__ qkv,
            uint32_t* __restrict__ oh, uint32_t* __restrict__ ol)
{
    float* smf = (float*)dynsm;
    float* Qs = smf;
    float* Ks = smf + 64 * ATT_PAD;
    float* Vs = smf + 2 * 64 * ATT_PAD;
    float* Ps = smf + 3 * 64 * ATT_PAD;

    const int tid = threadIdx.x;
    const int qt = blockIdx.x, h = blockIdx.y, b = blockIdx.z;
    const int ty = tid >> 4, tx = tid & 15;
    const long rowbase = (long)b * SS;
    const int  qoff = h << 6;

    for (int i = tid; i < 1024; i += 256) {
        int r = i >> 4, c4 = (i & 15) << 2;
        float4 v = *(const float4*)(qkv + (rowbase + qt * 64 + r) * 1536 + qoff + c4);
        *(float4*)&Qs[r * ATT_PAD + c4] = v;
    }

    float m_i[4] = {-1e30f, -1e30f, -1e30f, -1e30f};
    float l_i[4] = {0, 0, 0, 0};
    float O[4][4] = {};

    for (int kt = 0; kt <= qt; kt++) {
        __syncthreads();
        for (int i = tid; i < 1024; i += 256) {
            int r = i >> 4, c4 = (i & 15) << 2;
            long gr = (rowbase + kt * 64 + r) * 1536 + qoff;
            *(float4*)&Ks[r * ATT_PAD + c4] = *(const float4*)(qkv + gr + 512 + c4);
            *(float4*)&Vs[r * ATT_PAD + c4] = *(const float4*)(qkv + gr + 1024 + c4);
        }
        __syncthreads();

        float s[4][4] = {};
        const float* qb = Qs + ty * 4 * ATT_PAD;
        const float* kb = Ks + tx * 4 * ATT_PAD;
        #pragma unroll
        for (int d4 = 0; d4 < 16; d4++) {
            float4 qa[4], ka[4];
            #pragma unroll
            for (int i = 0; i < 4; i++) qa[i] = *(const float4*)(qb + i * ATT_PAD + d4 * 4);
            #pragma unroll
            for (int j = 0; j < 4; j++) ka[j] = *(const float4*)(kb + j * ATT_PAD + d4 * 4);
            #pragma unroll
            for (int i = 0; i < 4; i++)
                #pragma unroll
                for (int j = 0; j < 4; j++)
                    s[i][j] += qa[i].x*ka[j].x + qa[i].y*ka[j].y
                             + qa[i].z*ka[j].z + qa[i].w*ka[j].w;
        }

        const float scale = 0.125f;
        const bool diag = (kt == qt);
        #pragma unroll
        for (int i = 0; i < 4; i++) {
            int r = ty * 4 + i;
            float rm = -1e30f;
            #pragma unroll
            for (int j = 0; j < 4; j++) {
                float v = s[i][j] * scale;
                if (diag && (tx * 4 + j) > r) v = -1e30f;
                s[i][j] = v;
                rm = fmaxf(rm, v);
            }
            #pragma unroll
            for (int o = 8; o > 0; o >>= 1)
                rm = fmaxf(rm, __shfl_xor_sync(0xffffffffu, rm, o));
            float nm = fmaxf(m_i[i], rm);
            float sf = __expf(m_i[i] - nm);
            m_i[i] = nm;
            float rs = 0.f;
            #pragma unroll
            for (int j = 0; j < 4; j++) {
                float pp = __expf(s[i][j] - nm);
                s[i][j] = pp; rs += pp;
            }
            #pragma unroll
            for (int o = 8; o > 0; o >>= 1)
                rs += __shfl_xor_sync(0xffffffffu, rs, o);
            l_i[i] = l_i[i] * sf + rs;
            #pragma unroll
            for (int j = 0; j < 4; j++) O[i][j] *= sf;
            *(float4*)&Ps[r * ATT_PAD + tx * 4] =
                make_float4(s[i][0], s[i][1], s[i][2], s[i][3]);
        }
        __syncthreads();

        #pragma unroll
        for (int c4 = 0; c4 < 16; c4++) {
            float4 pv[4];
            #pragma unroll
            for (int i = 0; i < 4; i++)
                pv[i] = *(const float4*)&Ps[(ty * 4 + i) * ATT_PAD + c4 * 4];
            #pragma unroll
            for (int cc = 0; cc < 4; cc++) {
                float4 vv = *(const float4*)&Vs[(c4 * 4 + cc) * ATT_PAD + tx * 4];
                #pragma unroll
                for (int i = 0; i < 4; i++) {
                    float pp = (cc == 0) ? pv[i].x : (cc == 1) ? pv[i].y
                             : (cc == 2) ? pv[i].z : pv[i].w;
                    O[i][0] += pp * vv.x; O[i][1] += pp * vv.y;
                    O[i][2] += pp * vv.z; O[i][3] += pp * vv.w;
                }
            }
        }
    }

    #pragma unroll
    for (int i = 0; i < 4; i++) {
        int r = ty * 4 + i;
        float inv = 1.0f / l_i[i];
        long widx = ((rowbase + qt * 64 + r) * DD + qoff + tx * 4) >> 1;
        uint32_t hw, lw;
        split2(O[i][0]*inv, O[i][1]*inv, hw, lw);
        oh[widx] = hw;     ol[widx] = lw;
        split2(O[i][2]*inv, O[i][3]*inv, hw, lw);
        oh[widx+1] = hw;   ol[widx+1] = lw;
    }
}

// ---------------------------------------------------------------------------
extern "C" void kernel_launch(void* const* d_in, const int* in_sizes, int n_in,
                              void* d_out, int out_size)
{
    const int*   x    = (const int*)  d_in[0];
    const float* emb  = (const float*)d_in[1];
    const float* pe   = (const float*)d_in[2];
    const float* Wqkv = (const float*)d_in[3];
    const float* Wo   = (const float*)d_in[4];
    const float* bo   = (const float*)d_in[5];
    const float* g1   = (const float*)d_in[6];
    const float* b1   = (const float*)d_in[7];
    const float* g2   = (const float*)d_in[8];
    const float* b2   = (const float*)d_in[9];
    const float* W1   = (const float*)d_in[10];
    const float* bf1  = (const float*)d_in[11];
    const float* W2   = (const float*)d_in[12];
    const float* bf2  = (const float*)d_in[13];
    const float* gf   = (const float*)d_in[14];
    const float* bfp  = (const float*)d_in[15];
    const float* Wout = (const float*)d_in[16];
    const float* bfc  = (const float*)d_in[17];
    float* out = (float*)d_out;

    float *h, *big, *t;
    cudaGetSymbolAddress((void**)&h,   g_h);
    cudaGetSymbolAddress((void**)&big, g_big);
    cudaGetSymbolAddress((void**)&t,   g_t);
    __nv_bfloat16 *hh, *hl, *oh, *ol, *fh, *fl, *th, *tl;
    cudaGetSymbolAddress((void**)&hh, g_hh);  cudaGetSymbolAddress((void**)&hl, g_hl);
    cudaGetSymbolAddress((void**)&oh, g_oh);  cudaGetSymbolAddress((void**)&ol, g_ol);
    cudaGetSymbolAddress((void**)&fh, g_fh);  cudaGetSymbolAddress((void**)&fl, g_fl);
    cudaGetSymbolAddress((void**)&th, g_th);  cudaGetSymbolAddress((void**)&tl, g_tl);
    __nv_bfloat16 *qkvTh, *qkvTl, *woTh, *woTl, *w1Th, *w1Tl, *w2Th, *w2Tl, *outTh, *outTl;
    cudaGetSymbolAddress((void**)&qkvTh, g_qkvT_h);
    cudaGetSymbolAddress((void**)&qkvTl, g_qkvT_l);
    cudaGetSymbolAddress((void**)&woTh,  g_woT_h);
    cudaGetSymbolAddress((void**)&woTl,  g_woT_l);
    cudaGetSymbolAddress((void**)&w1Th,  g_w1T_h);
    cudaGetSymbolAddress((void**)&w1Tl,  g_w1T_l);
    cudaGetSymbolAddress((void**)&w2Th,  g_w2T_h);
    cudaGetSymbolAddress((void**)&w2Tl,  g_w2T_l);
    cudaGetSymbolAddress((void**)&outTh, g_outT_h);
    cudaGetSymbolAddress((void**)&outTl, g_outT_l);

    cudaFuncSetAttribute(attn_k, cudaFuncAttributeMaxDynamicSharedMemorySize, ATT_SMEM);
    cudaFuncSetAttribute(gemm_bf16<0,0>, cudaFuncAttributeMaxDynamicSharedMemorySize, GEMM_SMEM);
    cudaFuncSetAttribute(gemm_bf16<1,1>, cudaFuncAttributeMaxDynamicSharedMemorySize, GEMM_SMEM);

    // weight prep: transpose + bf16 split
    wprep_k<<<dim3(3*DD/32, DD/32, LL), 256>>>(Wqkv, qkvTh, qkvTl, DD, 3*DD);
    wprep_k<<<dim3(DD/32,   DD/32, LL), 256>>>(Wo,   woTh,  woTl,  DD, DD);
    wprep_k<<<dim3(FF/32,   DD/32, LL), 256>>>(W1,   w1Th,  w1Tl,  DD, FF);
    wprep_k<<<dim3(DD/32,   FF/32, LL), 256>>>(W2,   w2Th,  w2Tl,  FF, DD);
    wprep_k<<<dim3(VV/32,   DD/32, 1 ), 256>>>(Wout, outTh, outTl, DD, VV);

    embed_k<<<ROWS, 128>>>(x, emb, pe, h, (uint32_t*)hh, (uint32_t*)hl);

    for (int l = 0; l < LL; l++) {
        // QKV: [4096,512] x [1536,512]^T -> fp32 big
        gemm_bf16<0,0><<<dim3(32, 12), 256, GEMM_SMEM>>>(
            hh, hl, qkvTh + (long)l * 3*DD*DD, qkvTl + (long)l * 3*DD*DD,
            nullptr, big, nullptr, nullptr, ROWS, 3*DD, DD);
        // attention -> hi/lo planes
        attn_k<<<dim3(SS / 64, HH, BB), 256, ATT_SMEM>>>(
            big, (uint32_t*)oh, (uint32_t*)ol);
        // Wo -> fp32 t
        gemm_bf16<0,0><<<dim3(32, 4), 256, GEMM_SMEM>>>(
            oh, ol, woTh + (long)l * DD*DD, woTl + (long)l * DD*DD,
            bo + l * DD, t, nullptr, nullptr, ROWS, DD, DD);
        // h = LN(h + attn) -> fp32 + planes
        add_ln_k<<<ROWS, 128>>>(t, h, g1 + l * DD, b1 + l * DD,
                                h, (uint32_t*)hh, (uint32_t*)hl);
        // FF1 + relu -> hi/lo planes
        gemm_bf16<1,1><<<dim3(32, 16), 256, GEMM_SMEM>>>(
            hh, hl, w1Th + (long)l * FF*DD, w1Tl + (long)l * FF*DD,
            bf1 + l * FF, nullptr, (uint32_t*)fh, (uint32_t*)fl, ROWS, FF, DD);
        // FF2 -> fp32 t
        gemm_bf16<0,0><<<dim3(32, 4), 256, GEMM_SMEM>>>(
            fh, fl, w2Th + (long)l * DD*FF, w2Tl + (long)l * DD*FF,
            bf2 + l * DD, t, nullptr, nullptr, ROWS, DD, FF);
        // h = LN(h + ff) -> fp32 + planes
        add_ln_k<<<ROWS, 128>>>(t, h, g2 + l * DD, b2 + l * DD,
                                h, (uint32_t*)hh, (uint32_t*)hl);
    }

    // final LN -> planes th/tl
    add_ln_k<<<ROWS, 128>>>(h, nullptr, gf, bfp, t, (uint32_t*)th, (uint32_t*)tl);
    // logits: [4096,512] x [32000,512]^T + bfc -> out fp32
    gemm_bf16<0,0><<<dim3(32, 250), 256, GEMM_SMEM>>>(
        th, tl, outTh, outTl, bfc, out, nullptr, nullptr, ROWS, VV, DD);
}

// round 7
// speedup vs baseline: 2.5384x; 1.5474x over previous
#include <cuda_runtime.h>
#include <cuda_bf16.h>
#include <cstdint>

#define BB 2
#define SS 2048
#define DD 512
#define LL 6
#define HH 8
#define FF 2048
#define VV 32000
#define ROWS (BB*SS)   // 4096

// fp32 residual stream scratch
__device__ float g_h [ROWS * DD];
__device__ float g_t [ROWS * DD];
// packed bf16 hi/lo activation planes
__device__ __align__(16) __nv_bfloat16 g_hh [ROWS * DD],  g_hl [ROWS * DD];
__device__ __align__(16) __nv_bfloat16 g_qh [ROWS * 3*DD], g_ql [ROWS * 3*DD]; // qkv planes
__device__ __align__(16) __nv_bfloat16 g_oh [ROWS * DD],  g_ol [ROWS * DD];
__device__ __align__(16) __nv_bfloat16 g_fh [ROWS * FF],  g_fl [ROWS * FF];
__device__ __align__(16) __nv_bfloat16 g_th [ROWS * DD],  g_tl [ROWS * DD];
// pre-transposed bf16-split weights: [N][K] row-major
__device__ __align__(16) __nv_bfloat16 g_qkvT_h[LL * 3*DD * DD], g_qkvT_l[LL * 3*DD * DD];
__device__ __align__(16) __nv_bfloat16 g_woT_h [LL * DD * DD],   g_woT_l [LL * DD * DD];
__device__ __align__(16) __nv_bfloat16 g_w1T_h [LL * FF * DD],   g_w1T_l [LL * FF * DD];
__device__ __align__(16) __nv_bfloat16 g_w2T_h [LL * DD * FF],   g_w2T_l [LL * DD * FF];
__device__ __align__(16) __nv_bfloat16 g_outT_h[VV * DD],        g_outT_l[VV * DD];

extern __shared__ char dynsm[];

// ---------------------------------------------------------------------------
__device__ __forceinline__ uint32_t smem_u32(const void* p) {
    uint32_t a;
    asm("{ .reg .u64 t; cvta.to.shared.u64 t, %1; cvt.u32.u64 %0, t; }"
        : "=r"(a) : "l"(p));
    return a;
}
__device__ __forceinline__ void cpa16(uint32_t s, const void* g) {
    asm volatile("cp.async.cg.shared.global [%0], [%1], 16;" :: "r"(s), "l"(g));
}
__device__ __forceinline__ void split2(float x0, float x1, uint32_t& hw, uint32_t& lw) {
    __nv_bfloat16 h0 = __float2bfloat16(x0), h1 = __float2bfloat16(x1);
    __nv_bfloat16 l0 = __float2bfloat16(x0 - __bfloat162float(h0));
    __nv_bfloat16 l1 = __float2bfloat16(x1 - __bfloat162float(h1));
    __nv_bfloat162 hp(h0, h1), lp(l0, l1);
    hw = *(uint32_t*)&hp;
    lw = *(uint32_t*)&lp;
}
__device__ __forceinline__ void mma_bf16(float* d, const uint32_t* a, const uint32_t* b) {
    asm volatile("mma.sync.aligned.m16n8k16.row.col.f32.bf16.bf16.f32 "
        "{%0,%1,%2,%3}, {%4,%5,%6,%7}, {%8,%9}, {%0,%1,%2,%3};"
        : "+f"(d[0]), "+f"(d[1]), "+f"(d[2]), "+f"(d[3])
        : "r"(a[0]), "r"(a[1]), "r"(a[2]), "r"(a[3]), "r"(b[0]), "r"(b[1]));
}

// ---------------------------------------------------------------------------
// Weight prep: W[K,N] fp32 -> WT hi/lo [N,K] bf16
// ---------------------------------------------------------------------------
__global__ void wprep_k(const float* __restrict__ W, __nv_bfloat16* __restrict__ hi,
                        __nv_bfloat16* __restrict__ lo, int K, int N)
{
    __shared__ float ts[32][33];
    long moff = (long)blockIdx.z * K * N;
    int kb = blockIdx.y * 32, nb = blockIdx.x * 32;
    int r = threadIdx.x >> 5, c = threadIdx.x & 31;
    #pragma unroll
    for (int i = 0; i < 4; i++)
        ts[r + i*8][c] = W[moff + (long)(kb + r + i*8) * N + nb + c];
    __syncthreads();
    #pragma unroll
    for (int i = 0; i < 4; i++) {
        int n = r + i*8;
        float x = ts[c][n];
        __nv_bfloat16 h = __float2bfloat16(x);
        __nv_bfloat16 l = __float2bfloat16(x - __bfloat162float(h));
        long oidx = moff + (long)(nb + n) * K + kb + c;
        hi[oidx] = h;
        lo[oidx] = l;
    }
}

// ---------------------------------------------------------------------------
// Embedding + PE -> fp32 h + hi/lo planes
// ---------------------------------------------------------------------------
__global__ void embed_k(const int* __restrict__ x, const float* __restrict__ emb,
                        const float* __restrict__ pe, float* __restrict__ h,
                        uint32_t* __restrict__ oh, uint32_t* __restrict__ ol)
{
    int row = blockIdx.x, tid = threadIdx.x;
    int s   = row & (SS - 1);
    int tok = x[row];
    float4 ev = ((const float4*)(emb + (long)tok * DD))[tid];
    float4 pv = ((const float4*)(pe  + (long)s   * DD))[tid];
    float4 o;
    o.x = ev.x + pv.x; o.y = ev.y + pv.y; o.z = ev.z + pv.z; o.w = ev.w + pv.w;
    ((float4*)(h + (long)row * DD))[tid] = o;
    uint32_t hw, lw;
    int wi = row * (DD/2) + tid * 2;
    split2(o.x, o.y, hw, lw); oh[wi] = hw;   ol[wi] = lw;
    split2(o.z, o.w, hw, lw); oh[wi+1] = hw; ol[wi+1] = lw;
}

// ---------------------------------------------------------------------------
// out = LayerNorm(x (+ res)) * g + b -> fp32 + hi/lo planes
// ---------------------------------------------------------------------------
__global__ void add_ln_k(const float* __restrict__ x, const float* __restrict__ res,
                         const float* __restrict__ gg, const float* __restrict__ bb,
                         float* __restrict__ outF,
                         uint32_t* __restrict__ outH, uint32_t* __restrict__ outL)
{
    int row = blockIdx.x, tid = threadIdx.x;
    float4 v = ((const float4*)(x + (long)row * DD))[tid];
    if (res) {
        float4 rv = ((const float4*)(res + (long)row * DD))[tid];
        v.x += rv.x; v.y += rv.y; v.z += rv.z; v.w += rv.w;
    }
    float s  = v.x + v.y + v.z + v.w;
    float s2 = v.x*v.x + v.y*v.y + v.z*v.z + v.w*v.w;
    #pragma unroll
    for (int o = 16; o; o >>= 1) {
        s  += __shfl_xor_sync(0xffffffffu, s,  o);
        s2 += __shfl_xor_sync(0xffffffffu, s2, o);
    }
    __shared__ float ssum[4], ssq[4];
    int wid = tid >> 5;
    if ((tid & 31) == 0) { ssum[wid] = s; ssq[wid] = s2; }
    __syncthreads();
    s  = ssum[0] + ssum[1] + ssum[2] + ssum[3];
    s2 = ssq[0]  + ssq[1]  + ssq[2]  + ssq[3];
    float mean = s * (1.0f / DD);
    float var  = s2 * (1.0f / DD) - mean * mean;
    float inv  = rsqrtf(var + 1e-5f);
    float4 gv = ((const float4*)gg)[tid];
    float4 bv = ((const float4*)bb)[tid];
    float4 o;
    o.x = (v.x - mean) * inv * gv.x + bv.x;
    o.y = (v.y - mean) * inv * gv.y + bv.y;
    o.z = (v.z - mean) * inv * gv.z + bv.z;
    o.w = (v.w - mean) * inv * gv.w + bv.w;
    ((float4*)(outF + (long)row * DD))[tid] = o;
    uint32_t hw, lw;
    int wi = row * (DD/2) + tid * 2;
    split2(o.x, o.y, hw, lw); outH[wi] = hw;   outL[wi] = lw;
    split2(o.z, o.w, hw, lw); outH[wi+1] = hw; outL[wi+1] = lw;
}

// ---------------------------------------------------------------------------
// bf16 3-term tensor GEMM (unchanged from round 6, proven)
// ---------------------------------------------------------------------------
#define GSTR 20
#define GPL  (128*GSTR)
#define GEMM_SMEM (8*GPL*4)

template<int RELU, int OUTMODE>
__global__ __launch_bounds__(256)
void gemm_bf16(const __nv_bfloat16* __restrict__ Ahp, const __nv_bfloat16* __restrict__ Alp,
               const __nv_bfloat16* __restrict__ Bhp, const __nv_bfloat16* __restrict__ Blp,
               const float* __restrict__ bias,
               float* __restrict__ C, uint32_t* __restrict__ Chw, uint32_t* __restrict__ Clw,
               int M, int N, int K)
{
    uint32_t* sm = (uint32_t*)dynsm;
    const int tid = threadIdx.x, warp = tid >> 5, lane = tid & 31;
    const int g = lane >> 2, c = lane & 3;
    const int bm = blockIdx.x * 128, bn = blockIdx.y * 128;
    const int wm = (warp >> 2) * 64, wn = (warp & 3) * 32;
    const uint32_t sb = smem_u32(sm);
    const int T = K / 32;

    auto stage = [&](int t, int b) {
        #pragma unroll
        for (int i = 0; i < 2; i++) {
            int id = tid + 256 * i, row = id >> 2, cc = id & 3;
            uint32_t doff = (uint32_t)(row * GSTR + cc * 4) * 4;
            uint32_t dbase = sb + (uint32_t)(b * 4 * GPL) * 4 + doff;
            long asrc = (long)(bm + row) * K + t * 32 + cc * 8;
            long bsrc = (long)(bn + row) * K + t * 32 + cc * 8;
            cpa16(dbase,             Ahp + asrc);
            cpa16(dbase + GPL*4,     Alp + asrc);
            cpa16(dbase + 2*GPL*4,   Bhp + bsrc);
            cpa16(dbase + 3*GPL*4,   Blp + bsrc);
        }
        asm volatile("cp.async.commit_group;");
    };

    float acc[4][4][4] = {};

    stage(0, 0);
    if (T > 1) stage(1, 1);

    for (int t = 0; t < T; t++) {
        if (t + 1 < T) asm volatile("cp.async.wait_group 1;");
        else           asm volatile("cp.async.wait_group 0;");
        __syncthreads();

        const uint32_t* Ahs = sm + (t & 1) * 4 * GPL;
        const uint32_t* Als = Ahs + GPL;
        const uint32_t* Bhs = Ahs + 2 * GPL;
        const uint32_t* Bls = Ahs + 3 * GPL;

        #pragma unroll
        for (int kk = 0; kk < 2; kk++) {
            uint32_t ah[4][4], al[4][4];
            #pragma unroll
            for (int mt = 0; mt < 4; mt++) {
                int ar = (wm + mt*16 + g) * GSTR + kk*8 + c;
                ah[mt][0] = Ahs[ar];     ah[mt][1] = Ahs[ar + 8*GSTR];
                ah[mt][2] = Ahs[ar + 4]; ah[mt][3] = Ahs[ar + 8*GSTR + 4];
                al[mt][0] = Als[ar];     al[mt][1] = Als[ar + 8*GSTR];
                al[mt][2] = Als[ar + 4]; al[mt][3] = Als[ar + 8*GSTR + 4];
            }
            #pragma unroll
            for (int nt = 0; nt < 4; nt++) {
                int br = (wn + nt*8 + g) * GSTR + kk*8 + c;
                uint32_t bh[2] = {Bhs[br], Bhs[br + 4]};
                uint32_t bl[2] = {Bls[br], Bls[br + 4]};
                #pragma unroll
                for (int mt = 0; mt < 4; mt++) {
                    mma_bf16(acc[mt][nt], ah[mt], bh);
                    mma_bf16(acc[mt][nt], ah[mt], bl);
                    mma_bf16(acc[mt][nt], al[mt], bh);
                }
            }
        }
        __syncthreads();
        if (t + 2 < T) stage(t + 2, t & 1);
    }

    #pragma unroll
    for (int mt = 0; mt < 4; mt++) {
        #pragma unroll
        for (int nt = 0; nt < 4; nt++) {
            int col = bn + wn + nt*8 + 2*c;
            float bx = 0.f, by = 0.f;
            if (bias) { bx = bias[col]; by = bias[col + 1]; }
            long r0 = bm + wm + mt*16 + g;
            float v0 = acc[mt][nt][0] + bx, v1 = acc[mt][nt][1] + by;
            float v2 = acc[mt][nt][2] + bx, v3 = acc[mt][nt][3] + by;
            if (RELU) {
                v0 = fmaxf(v0, 0.f); v1 = fmaxf(v1, 0.f);
                v2 = fmaxf(v2, 0.f); v3 = fmaxf(v3, 0.f);
            }
            if (OUTMODE == 0) {
                *(float2*)(C + r0 * N + col)       = make_float2(v0, v1);
                *(float2*)(C + (r0 + 8) * N + col) = make_float2(v2, v3);
            } else {
                uint32_t hw, lw;
                split2(v0, v1, hw, lw);
                Chw[(r0 * N + col) >> 1] = hw; Clw[(r0 * N + col) >> 1] = lw;
                split2(v2, v3, hw, lw);
                Chw[((r0 + 8) * N + col) >> 1] = hw; Clw[((r0 + 8) * N + col) >> 1] = lw;
            }
        }
    }
}

// ---------------------------------------------------------------------------
// mma flash attention. CTA = 128 q-rows x (head, batch). 8 warps x 16 rows.
// QKV in bf16 hi/lo planes [row][1536]. S = QK^T and P.V via m16n8k16, 3-term.
// P stays in registers (C-frag == A-frag layout). V^T staged in smem.
// ---------------------------------------------------------------------------
#define ASTR 36                       // smem word stride per 64-bf16 row
#define AQH 0
#define AQL (128*ASTR)                // 4608
#define AKH (2*128*ASTR)              // 9216
#define AKL (AKH + 64*ASTR)
#define AVH (AKH + 2*64*ASTR)
#define AVL (AKH + 3*64*ASTR)
#define ATT_SMEM ((2*128*ASTR + 4*64*ASTR)*4)   // 73728 B

__global__ __launch_bounds__(256)
void attn_mma(const __nv_bfloat16* __restrict__ qh, const __nv_bfloat16* __restrict__ ql,
              uint32_t* __restrict__ oh, uint32_t* __restrict__ ol)
{
    uint32_t* sm = (uint32_t*)dynsm;
    const uint32_t sb = smem_u32(sm);
    const int tid = threadIdx.x, warp = tid >> 5, lane = tid & 31;
    const int g = lane >> 2, c = lane & 3;
    const int qt = (int)gridDim.x - 1 - (int)blockIdx.x;   // big tiles first
    const int h = blockIdx.y, b = blockIdx.z;
    const long rowbase = (long)b * SS;
    const int qoff = h << 6;

    // stage Q (128 rows x 64, hi+lo)
    #pragma unroll
    for (int p = 0; p < 2; p++) {
        const __nv_bfloat16* src = p ? ql : qh;
        uint32_t dst = sb + (p ? AQL : AQH) * 4;
        #pragma unroll
        for (int i = 0; i < 4; i++) {
            int id = tid + 256 * i;
            int row = id >> 3, ch = id & 7;
            cpa16(dst + (uint32_t)(row * ASTR + ch * 4) * 4,
                  src + (rowbase + qt * 128 + row) * 1536 + qoff + ch * 8);
        }
    }
    asm volatile("cp.async.commit_group;");

    float m0 = -1e30f, m1 = -1e30f, l0 = 0.f, l1 = 0.f;
    float O[8][4] = {};
    const int nk = 2 * qt + 2;
    const int rbase = qt * 128 + warp * 16;

    for (int kt = 0; kt < nk; kt++) {
        // ---- stage K (cp.async) ----
        #pragma unroll
        for (int i = 0; i < 4; i++) {
            int id = tid + 256 * i;
            int p = id >> 9, rem = id & 511;
            int row = rem >> 3, ch = rem & 7;
            const __nv_bfloat16* src = p ? ql : qh;
            uint32_t dst = sb + (uint32_t)((p ? AKL : AKH) + row * ASTR + ch * 4) * 4;
            cpa16(dst, src + (rowbase + kt * 64 + row) * 1536 + 512 + qoff + ch * 8);
        }
        asm volatile("cp.async.commit_group;");
        // ---- stage V^T (SIMT transpose) ----
        {
            int key = tid & 63, sec = tid >> 6;
            int dh0 = sec * 16;
            long base = (rowbase + kt * 64 + key) * 1536 + 1024 + qoff + dh0;
            #pragma unroll
            for (int p = 0; p < 2; p++) {
                const __nv_bfloat16* src = p ? ql : qh;
                __nv_bfloat16* vt = (__nv_bfloat16*)(sm + (p ? AVL : AVH));
                uint4 v0 = *(const uint4*)(src + base);
                uint4 v1 = *(const uint4*)(src + base + 8);
                const __nv_bfloat16* e0 = (const __nv_bfloat16*)&v0;
                const __nv_bfloat16* e1 = (const __nv_bfloat16*)&v1;
                #pragma unroll
                for (int j = 0; j < 8; j++) {
                    vt[(dh0 + j) * (2*ASTR) + key]     = e0[j];
                    vt[(dh0 + 8 + j) * (2*ASTR) + key] = e1[j];
                }
            }
        }
        asm volatile("cp.async.wait_group 0;");
        __syncthreads();

        // ---- S = Q K^T (16x64 per warp), 3-term ----
        float sacc[8][4] = {};
        const uint32_t* Qh = sm + AQH;
        const uint32_t* Ql = sm + AQL;
        const uint32_t* Kh = sm + AKH;
        const uint32_t* Kl = sm + AKL;
        #pragma unroll
        for (int kk = 0; kk < 4; kk++) {
            int ar = (warp * 16 + g) * ASTR + kk * 8 + c;
            uint32_t ah[4] = {Qh[ar], Qh[ar + 8*ASTR], Qh[ar + 4], Qh[ar + 8*ASTR + 4]};
            uint32_t al[4] = {Ql[ar], Ql[ar + 8*ASTR], Ql[ar + 4], Ql[ar + 8*ASTR + 4]};
            #pragma unroll
            for (int nt = 0; nt < 8; nt++) {
                int br = (nt * 8 + g) * ASTR + kk * 8 + c;
                uint32_t bh[2] = {Kh[br], Kh[br + 4]};
                uint32_t bl[2] = {Kl[br], Kl[br + 4]};
                mma_bf16(sacc[nt], ah, bh);
                mma_bf16(sacc[nt], ah, bl);
                mma_bf16(sacc[nt], al, bh);
            }
        }

        // ---- mask + online softmax ----
        const float scale = 0.125f;
        const bool diag = (kt >= 2 * qt);
        const int row0 = rbase + g, row1 = rbase + g + 8;
        const int colb = kt * 64 + 2 * c;
        float rm0 = -1e30f, rm1 = -1e30f;
        #pragma unroll
        for (int nt = 0; nt < 8; nt++) {
            int c0 = colb + nt * 8;
            float v0 = sacc[nt][0] * scale, v1 = sacc[nt][1] * scale;
            float v2 = sacc[nt][2] * scale, v3 = sacc[nt][3] * scale;
            if (diag) {
                if (c0     > row0) v0 = -1e30f;
                if (c0 + 1 > row0) v1 = -1e30f;
                if (c0     > row1) v2 = -1e30f;
                if (c0 + 1 > row1) v3 = -1e30f;
            }
            sacc[nt][0] = v0; sacc[nt][1] = v1; sacc[nt][2] = v2; sacc[nt][3] = v3;
            rm0 = fmaxf(rm0, fmaxf(v0, v1));
            rm1 = fmaxf(rm1, fmaxf(v2, v3));
        }
        #pragma unroll
        for (int o = 1; o < 4; o <<= 1) {
            rm0 = fmaxf(rm0, __shfl_xor_sync(0xffffffffu, rm0, o));
            rm1 = fmaxf(rm1, __shfl_xor_sync(0xffffffffu, rm1, o));
        }
        float nm0 = fmaxf(m0, rm0), nm1 = fmaxf(m1, rm1);
        float sf0 = __expf(m0 - nm0), sf1 = __expf(m1 - nm1);
        m0 = nm0; m1 = nm1;
        float rs0 = 0.f, rs1 = 0.f;
        #pragma unroll
        for (int nt = 0; nt < 8; nt++) {
            float p0 = __expf(sacc[nt][0] - nm0);
            float p1 = __expf(sacc[nt][1] - nm0);
            float p2 = __expf(sacc[nt][2] - nm1);
            float p3 = __expf(sacc[nt][3] - nm1);
            sacc[nt][0] = p0; sacc[nt][1] = p1; sacc[nt][2] = p2; sacc[nt][3] = p3;
            rs0 += p0 + p1; rs1 += p2 + p3;
        }
        #pragma unroll
        for (int o = 1; o < 4; o <<= 1) {
            rs0 += __shfl_xor_sync(0xffffffffu, rs0, o);
            rs1 += __shfl_xor_sync(0xffffffffu, rs1, o);
        }
        l0 = l0 * sf0 + rs0;
        l1 = l1 * sf1 + rs1;
        #pragma unroll
        for (int nt = 0; nt < 8; nt++) {
            O[nt][0] *= sf0; O[nt][1] *= sf0;
            O[nt][2] *= sf1; O[nt][3] *= sf1;
        }

        // ---- O += P V  (P in registers: C-frag -> A-frag) ----
        const uint32_t* Vh = sm + AVH;
        const uint32_t* Vl = sm + AVL;
        #pragma unroll
        for (int kk = 0; kk < 4; kk++) {
            uint32_t ah[4], al[4];
            split2(sacc[2*kk][0],   sacc[2*kk][1],   ah[0], al[0]);
            split2(sacc[2*kk][2],   sacc[2*kk][3],   ah[1], al[1]);
            split2(sacc[2*kk+1][0], sacc[2*kk+1][1], ah[2], al[2]);
            split2(sacc[2*kk+1][2], sacc[2*kk+1][3], ah[3], al[3]);
            #pragma unroll
            for (int nt = 0; nt < 8; nt++) {
                int br = (nt * 8 + g) * ASTR + kk * 8 + c;
                uint32_t bh[2] = {Vh[br], Vh[br + 4]};
                uint32_t bl[2] = {Vl[br], Vl[br + 4]};
                mma_bf16(O[nt], ah, bh);
                mma_bf16(O[nt], ah, bl);
                mma_bf16(O[nt], al, bh);
            }
        }
        __syncthreads();
    }

    // ---- epilogue: O/l -> hi/lo planes ----
    float inv0 = 1.0f / l0, inv1 = 1.0f / l1;
    long grow0 = rowbase + rbase + g;
    #pragma unroll
    for (int nt = 0; nt < 8; nt++) {
        int col = qoff + nt * 8 + 2 * c;
        uint32_t hw, lw;
        split2(O[nt][0] * inv0, O[nt][1] * inv0, hw, lw);
        oh[(grow0 * DD + col) >> 1] = hw;
        ol[(grow0 * DD + col) >> 1] = lw;
        split2(O[nt][2] * inv1, O[nt][3] * inv1, hw, lw);
        oh[((grow0 + 8) * DD + col) >> 1] = hw;
        ol[((grow0 + 8) * DD + col) >> 1] = lw;
    }
}

// ---------------------------------------------------------------------------
extern "C" void kernel_launch(void* const* d_in, const int* in_sizes, int n_in,
                              void* d_out, int out_size)
{
    const int*   x    = (const int*)  d_in[0];
    const float* emb  = (const float*)d_in[1];
    const float* pe   = (const float*)d_in[2];
    const float* Wqkv = (const float*)d_in[3];
    const float* Wo   = (const float*)d_in[4];
    const float* bo   = (const float*)d_in[5];
    const float* g1   = (const float*)d_in[6];
    const float* b1   = (const float*)d_in[7];
    const float* g2   = (const float*)d_in[8];
    const float* b2   = (const float*)d_in[9];
    const float* W1   = (const float*)d_in[10];
    const float* bf1  = (const float*)d_in[11];
    const float* W2   = (const float*)d_in[12];
    const float* bf2  = (const float*)d_in[13];
    const float* gf   = (const float*)d_in[14];
    const float* bfp  = (const float*)d_in[15];
    const float* Wout = (const float*)d_in[16];
    const float* bfc  = (const float*)d_in[17];
    float* out = (float*)d_out;

    float *h, *t;
    cudaGetSymbolAddress((void**)&h, g_h);
    cudaGetSymbolAddress((void**)&t, g_t);
    __nv_bfloat16 *hh, *hl, *qh, *ql, *oh, *ol, *fh, *fl, *th, *tl;
    cudaGetSymbolAddress((void**)&hh, g_hh);  cudaGetSymbolAddress((void**)&hl, g_hl);
    cudaGetSymbolAddress((void**)&qh, g_qh);  cudaGetSymbolAddress((void**)&ql, g_ql);
    cudaGetSymbolAddress((void**)&oh, g_oh);  cudaGetSymbolAddress((void**)&ol, g_ol);
    cudaGetSymbolAddress((void**)&fh, g_fh);  cudaGetSymbolAddress((void**)&fl, g_fl);
    cudaGetSymbolAddress((void**)&th, g_th);  cudaGetSymbolAddress((void**)&tl, g_tl);
    __nv_bfloat16 *qkvTh, *qkvTl, *woTh, *woTl, *w1Th, *w1Tl, *w2Th, *w2Tl, *outTh, *outTl;
    cudaGetSymbolAddress((void**)&qkvTh, g_qkvT_h);
    cudaGetSymbolAddress((void**)&qkvTl, g_qkvT_l);
    cudaGetSymbolAddress((void**)&woTh,  g_woT_h);
    cudaGetSymbolAddress((void**)&woTl,  g_woT_l);
    cudaGetSymbolAddress((void**)&w1Th,  g_w1T_h);
    cudaGetSymbolAddress((void**)&w1Tl,  g_w1T_l);
    cudaGetSymbolAddress((void**)&w2Th,  g_w2T_h);
    cudaGetSymbolAddress((void**)&w2Tl,  g_w2T_l);
    cudaGetSymbolAddress((void**)&outTh, g_outT_h);
    cudaGetSymbolAddress((void**)&outTl, g_outT_l);

    cudaFuncSetAttribute(attn_mma, cudaFuncAttributeMaxDynamicSharedMemorySize, ATT_SMEM);
    cudaFuncSetAttribute(gemm_bf16<0,0>, cudaFuncAttributeMaxDynamicSharedMemorySize, GEMM_SMEM);
    cudaFuncSetAttribute(gemm_bf16<0,1>, cudaFuncAttributeMaxDynamicSharedMemorySize, GEMM_SMEM);
    cudaFuncSetAttribute(gemm_bf16<1,1>, cudaFuncAttributeMaxDynamicSharedMemorySize, GEMM_SMEM);

    wprep_k<<<dim3(3*DD/32, DD/32, LL), 256>>>(Wqkv, qkvTh, qkvTl, DD, 3*DD);
    wprep_k<<<dim3(DD/32,   DD/32, LL), 256>>>(Wo,   woTh,  woTl,  DD, DD);
    wprep_k<<<dim3(FF/32,   DD/32, LL), 256>>>(W1,   w1Th,  w1Tl,  DD, FF);
    wprep_k<<<dim3(DD/32,   FF/32, LL), 256>>>(W2,   w2Th,  w2Tl,  FF, DD);
    wprep_k<<<dim3(VV/32,   DD/32, 1 ), 256>>>(Wout, outTh, outTl, DD, VV);

    embed_k<<<ROWS, 128>>>(x, emb, pe, h, (uint32_t*)hh, (uint32_t*)hl);

    for (int l = 0; l < LL; l++) {
        // QKV -> hi/lo planes
        gemm_bf16<0,1><<<dim3(32, 12), 256, GEMM_SMEM>>>(
            hh, hl, qkvTh + (long)l * 3*DD*DD, qkvTl + (long)l * 3*DD*DD,
            nullptr, nullptr, (uint32_t*)qh, (uint32_t*)ql, ROWS, 3*DD, DD);
        // mma attention -> hi/lo planes
        attn_mma<<<dim3(SS/128, HH, BB), 256, ATT_SMEM>>>(
            qh, ql, (uint32_t*)oh, (uint32_t*)ol);
        // Wo -> fp32 t
        gemm_bf16<0,0><<<dim3(32, 4), 256, GEMM_SMEM>>>(
            oh, ol, woTh + (long)l * DD*DD, woTl + (long)l * DD*DD,
            bo + l * DD, t, nullptr, nullptr, ROWS, DD, DD);
        add_ln_k<<<ROWS, 128>>>(t, h, g1 + l * DD, b1 + l * DD,
                                h, (uint32_t*)hh, (uint32_t*)hl);
        // FF1 + relu -> hi/lo planes
        gemm_bf16<1,1><<<dim3(32, 16), 256, GEMM_SMEM>>>(
            hh, hl, w1Th + (long)l * FF*DD, w1Tl + (long)l * FF*DD,
            bf1 + l * FF, nullptr, (uint32_t*)fh, (uint32_t*)fl, ROWS, FF, DD);
        // FF2 -> fp32 t
        gemm_bf16<0,0><<<dim3(32, 4), 256, GEMM_SMEM>>>(
            fh, fl, w2Th + (long)l * DD*FF, w2Tl + (long)l * DD*FF,
            bf2 + l * DD, t, nullptr, nullptr, ROWS, DD, FF);
        add_ln_k<<<ROWS, 128>>>(t, h, g2 + l * DD, b2 + l * DD,
                                h, (uint32_t*)hh, (uint32_t*)hl);
    }

    add_ln_k<<<ROWS, 128>>>(h, nullptr, gf, bfp, t, (uint32_t*)th, (uint32_t*)tl);
    gemm_bf16<0,0><<<dim3(32, 250), 256, GEMM_SMEM>>>(
        th, tl, outTh, outTl, bfc, out, nullptr, nullptr, ROWS, VV, DD);
}

// round 8
// speedup vs baseline: 2.6973x; 1.0626x over previous
#include <cuda_runtime.h>
#include <cuda_bf16.h>
#include <cstdint>

#define BB 2
#define SS 2048
#define DD 512
#define LL 6
#define HH 8
#define FF 2048
#define VV 32000
#define ROWS (BB*SS)   // 4096

// fp32 residual stream scratch
__device__ float g_h [ROWS * DD];
__device__ float g_t [ROWS * DD];
// packed bf16 hi/lo activation planes
__device__ __align__(16) __nv_bfloat16 g_hh [ROWS * DD],  g_hl [ROWS * DD];
__device__ __align__(16) __nv_bfloat16 g_qh [ROWS * 3*DD], g_ql [ROWS * 3*DD];
__device__ __align__(16) __nv_bfloat16 g_oh [ROWS * DD],  g_ol [ROWS * DD];
__device__ __align__(16) __nv_bfloat16 g_fh [ROWS * FF],  g_fl [ROWS * FF];
__device__ __align__(16) __nv_bfloat16 g_th [ROWS * DD],  g_tl [ROWS * DD];
// pre-transposed bf16-split weights: [N][K] row-major
__device__ __align__(16) __nv_bfloat16 g_qkvT_h[LL * 3*DD * DD], g_qkvT_l[LL * 3*DD * DD];
__device__ __align__(16) __nv_bfloat16 g_woT_h [LL * DD * DD],   g_woT_l [LL * DD * DD];
__device__ __align__(16) __nv_bfloat16 g_w1T_h [LL * FF * DD],   g_w1T_l [LL * FF * DD];
__device__ __align__(16) __nv_bfloat16 g_w2T_h [LL * DD * FF],   g_w2T_l [LL * DD * FF];
__device__ __align__(16) __nv_bfloat16 g_outT_h[VV * DD],        g_outT_l[VV * DD];

extern __shared__ char dynsm[];

// ---------------------------------------------------------------------------
__device__ __forceinline__ uint32_t smem_u32(const void* p) {
    uint32_t a;
    asm("{ .reg .u64 t; cvta.to.shared.u64 t, %1; cvt.u32.u64 %0, t; }"
        : "=r"(a) : "l"(p));
    return a;
}
__device__ __forceinline__ void cpa16(uint32_t s, const void* g) {
    asm volatile("cp.async.cg.shared.global [%0], [%1], 16;" :: "r"(s), "l"(g));
}
__device__ __forceinline__ void split2(float x0, float x1, uint32_t& hw, uint32_t& lw) {
    __nv_bfloat16 h0 = __float2bfloat16(x0), h1 = __float2bfloat16(x1);
    __nv_bfloat16 l0 = __float2bfloat16(x0 - __bfloat162float(h0));
    __nv_bfloat16 l1 = __float2bfloat16(x1 - __bfloat162float(h1));
    __nv_bfloat162 hp(h0, h1), lp(l0, l1);
    hw = *(uint32_t*)&hp;
    lw = *(uint32_t*)&lp;
}
__device__ __forceinline__ void mma_bf16(float* d, const uint32_t* a, const uint32_t* b) {
    asm volatile("mma.sync.aligned.m16n8k16.row.col.f32.bf16.bf16.f32 "
        "{%0,%1,%2,%3}, {%4,%5,%6,%7}, {%8,%9}, {%0,%1,%2,%3};"
        : "+f"(d[0]), "+f"(d[1]), "+f"(d[2]), "+f"(d[3])
        : "r"(a[0]), "r"(a[1]), "r"(a[2]), "r"(a[3]), "r"(b[0]), "r"(b[1]));
}
__device__ __forceinline__ void ldm4(uint32_t* r, uint32_t a) {
    asm volatile("ldmatrix.sync.aligned.m8n8.x4.shared.b16 {%0,%1,%2,%3}, [%4];"
        : "=r"(r[0]), "=r"(r[1]), "=r"(r[2]), "=r"(r[3]) : "r"(a));
}
__device__ __forceinline__ void ldm4t(uint32_t* r, uint32_t a) {
    asm volatile("ldmatrix.sync.aligned.m8n8.x4.trans.shared.b16 {%0,%1,%2,%3}, [%4];"
        : "=r"(r[0]), "=r"(r[1]), "=r"(r[2]), "=r"(r[3]) : "r"(a));
}

// ---------------------------------------------------------------------------
// Weight prep: W[K,N] fp32 -> WT hi/lo [N,K] bf16
// ---------------------------------------------------------------------------
__global__ void wprep_k(const float* __restrict__ W, __nv_bfloat16* __restrict__ hi,
                        __nv_bfloat16* __restrict__ lo, int K, int N)
{
    __shared__ float ts[32][33];
    long moff = (long)blockIdx.z * K * N;
    int kb = blockIdx.y * 32, nb = blockIdx.x * 32;
    int r = threadIdx.x >> 5, c = threadIdx.x & 31;
    #pragma unroll
    for (int i = 0; i < 4; i++)
        ts[r + i*8][c] = W[moff + (long)(kb + r + i*8) * N + nb + c];
    __syncthreads();
    #pragma unroll
    for (int i = 0; i < 4; i++) {
        int n = r + i*8;
        float x = ts[c][n];
        __nv_bfloat16 h = __float2bfloat16(x);
        __nv_bfloat16 l = __float2bfloat16(x - __bfloat162float(h));
        long oidx = moff + (long)(nb + n) * K + kb + c;
        hi[oidx] = h;
        lo[oidx] = l;
    }
}

// ---------------------------------------------------------------------------
// Embedding + PE -> fp32 h + hi/lo planes
// ---------------------------------------------------------------------------
__global__ void embed_k(const int* __restrict__ x, const float* __restrict__ emb,
                        const float* __restrict__ pe, float* __restrict__ h,
                        uint32_t* __restrict__ oh, uint32_t* __restrict__ ol)
{
    int row = blockIdx.x, tid = threadIdx.x;
    int s   = row & (SS - 1);
    int tok = x[row];
    float4 ev = ((const float4*)(emb + (long)tok * DD))[tid];
    float4 pv = ((const float4*)(pe  + (long)s   * DD))[tid];
    float4 o;
    o.x = ev.x + pv.x; o.y = ev.y + pv.y; o.z = ev.z + pv.z; o.w = ev.w + pv.w;
    ((float4*)(h + (long)row * DD))[tid] = o;
    uint32_t hw, lw;
    int wi = row * (DD/2) + tid * 2;
    split2(o.x, o.y, hw, lw); oh[wi] = hw;   ol[wi] = lw;
    split2(o.z, o.w, hw, lw); oh[wi+1] = hw; ol[wi+1] = lw;
}

// ---------------------------------------------------------------------------
// out = LayerNorm(x (+ res)) * g + b -> fp32 + hi/lo planes
// ---------------------------------------------------------------------------
__global__ void add_ln_k(const float* __restrict__ x, const float* __restrict__ res,
                         const float* __restrict__ gg, const float* __restrict__ bb,
                         float* __restrict__ outF,
                         uint32_t* __restrict__ outH, uint32_t* __restrict__ outL)
{
    int row = blockIdx.x, tid = threadIdx.x;
    float4 v = ((const float4*)(x + (long)row * DD))[tid];
    if (res) {
        float4 rv = ((const float4*)(res + (long)row * DD))[tid];
        v.x += rv.x; v.y += rv.y; v.z += rv.z; v.w += rv.w;
    }
    float s  = v.x + v.y + v.z + v.w;
    float s2 = v.x*v.x + v.y*v.y + v.z*v.z + v.w*v.w;
    #pragma unroll
    for (int o = 16; o; o >>= 1) {
        s  += __shfl_xor_sync(0xffffffffu, s,  o);
        s2 += __shfl_xor_sync(0xffffffffu, s2, o);
    }
    __shared__ float ssum[4], ssq[4];
    int wid = tid >> 5;
    if ((tid & 31) == 0) { ssum[wid] = s; ssq[wid] = s2; }
    __syncthreads();
    s  = ssum[0] + ssum[1] + ssum[2] + ssum[3];
    s2 = ssq[0]  + ssq[1]  + ssq[2]  + ssq[3];
    float mean = s * (1.0f / DD);
    float var  = s2 * (1.0f / DD) - mean * mean;
    float inv  = rsqrtf(var + 1e-5f);
    float4 gv = ((const float4*)gg)[tid];
    float4 bv = ((const float4*)bb)[tid];
    float4 o;
    o.x = (v.x - mean) * inv * gv.x + bv.x;
    o.y = (v.y - mean) * inv * gv.y + bv.y;
    o.z = (v.z - mean) * inv * gv.z + bv.z;
    o.w = (v.w - mean) * inv * gv.w + bv.w;
    ((float4*)(outF + (long)row * DD))[tid] = o;
    uint32_t hw, lw;
    int wi = row * (DD/2) + tid * 2;
    split2(o.x, o.y, hw, lw); outH[wi] = hw;   outL[wi] = lw;
    split2(o.z, o.w, hw, lw); outH[wi+1] = hw; outL[wi+1] = lw;
}

// ---------------------------------------------------------------------------
// bf16 3-term tensor GEMM with ldmatrix fragment loads.
// C[M,N] = A[M,K] @ BT[N,K] (+bias)(+relu). 128x128x32 tiles, 8 warps.
// ---------------------------------------------------------------------------
#define GSTR 20
#define GPL  (128*GSTR)
#define GEMM_SMEM (8*GPL*4)

template<int RELU, int OUTMODE>
__global__ __launch_bounds__(256)
void gemm_bf16(const __nv_bfloat16* __restrict__ Ahp, const __nv_bfloat16* __restrict__ Alp,
               const __nv_bfloat16* __restrict__ Bhp, const __nv_bfloat16* __restrict__ Blp,
               const float* __restrict__ bias,
               float* __restrict__ C, uint32_t* __restrict__ Chw, uint32_t* __restrict__ Clw,
               int M, int N, int K)
{
    uint32_t* sm = (uint32_t*)dynsm;
    const int tid = threadIdx.x, warp = tid >> 5, lane = tid & 31;
    const int g = lane >> 2, c = lane & 3;
    const int bm = blockIdx.x * 128, bn = blockIdx.y * 128;
    const int wm = (warp >> 2) * 64, wn = (warp & 3) * 32;
    const uint32_t sb = smem_u32(sm);
    const int T = K / 32;

    // ldmatrix per-lane source coordinates
    const int alr = lane & 15, alw = (lane >> 4) * 4;              // A: row-in-16, k-half word
    const int blr = (lane & 7) + ((lane >> 4) << 3);               // B: row-in-16 (two n8)
    const int blw = ((lane >> 3) & 1) * 4;                         // B: k-half word

    auto stage = [&](int t, int b) {
        #pragma unroll
        for (int i = 0; i < 2; i++) {
            int id = tid + 256 * i, row = id >> 2, cc = id & 3;
            uint32_t doff = (uint32_t)(row * GSTR + cc * 4) * 4;
            uint32_t dbase = sb + (uint32_t)(b * 4 * GPL) * 4 + doff;
            long asrc = (long)(bm + row) * K + t * 32 + cc * 8;
            long bsrc = (long)(bn + row) * K + t * 32 + cc * 8;
            cpa16(dbase,             Ahp + asrc);
            cpa16(dbase + GPL*4,     Alp + asrc);
            cpa16(dbase + 2*GPL*4,   Bhp + bsrc);
            cpa16(dbase + 3*GPL*4,   Blp + bsrc);
        }
        asm volatile("cp.async.commit_group;");
    };

    float acc[4][4][4] = {};

    stage(0, 0);
    if (T > 1) stage(1, 1);

    for (int t = 0; t < T; t++) {
        if (t + 1 < T) asm volatile("cp.async.wait_group 1;");
        else           asm volatile("cp.async.wait_group 0;");
        __syncthreads();

        const uint32_t bufb = sb + (uint32_t)((t & 1) * 4 * GPL) * 4;

        #pragma unroll
        for (int kk = 0; kk < 2; kk++) {
            uint32_t ah[4][4], al[4][4];
            #pragma unroll
            for (int mt = 0; mt < 4; mt++) {
                uint32_t ao = (uint32_t)((wm + mt*16 + alr) * GSTR + kk*8 + alw) * 4;
                ldm4(ah[mt], bufb + ao);
                ldm4(al[mt], bufb + GPL*4 + ao);
            }
            #pragma unroll
            for (int pr = 0; pr < 2; pr++) {
                uint32_t bh[4], bl[4];
                uint32_t bo = (uint32_t)((wn + pr*16 + blr) * GSTR + kk*8 + blw) * 4;
                ldm4(bh, bufb + 2*GPL*4 + bo);
                ldm4(bl, bufb + 3*GPL*4 + bo);
                #pragma unroll
                for (int sub = 0; sub < 2; sub++) {
                    int nt = pr * 2 + sub;
                    #pragma unroll
                    for (int mt = 0; mt < 4; mt++) {
                        mma_bf16(acc[mt][nt], ah[mt], bh + 2*sub);
                        mma_bf16(acc[mt][nt], ah[mt], bl + 2*sub);
                        mma_bf16(acc[mt][nt], al[mt], bh + 2*sub);
                    }
                }
            }
        }
        __syncthreads();
        if (t + 2 < T) stage(t + 2, t & 1);
    }

    #pragma unroll
    for (int mt = 0; mt < 4; mt++) {
        #pragma unroll
        for (int nt = 0; nt < 4; nt++) {
            int col = bn + wn + nt*8 + 2*c;
            float bx = 0.f, by = 0.f;
            if (bias) { bx = bias[col]; by = bias[col + 1]; }
            long r0 = bm + wm + mt*16 + g;
            float v0 = acc[mt][nt][0] + bx, v1 = acc[mt][nt][1] + by;
            float v2 = acc[mt][nt][2] + bx, v3 = acc[mt][nt][3] + by;
            if (RELU) {
                v0 = fmaxf(v0, 0.f); v1 = fmaxf(v1, 0.f);
                v2 = fmaxf(v2, 0.f); v3 = fmaxf(v3, 0.f);
            }
            if (OUTMODE == 0) {
                *(float2*)(C + r0 * N + col)       = make_float2(v0, v1);
                *(float2*)(C + (r0 + 8) * N + col) = make_float2(v2, v3);
            } else {
                uint32_t hw, lw;
                split2(v0, v1, hw, lw);
                Chw[(r0 * N + col) >> 1] = hw; Clw[(r0 * N + col) >> 1] = lw;
                split2(v2, v3, hw, lw);
                Chw[((r0 + 8) * N + col) >> 1] = hw; Clw[((r0 + 8) * N + col) >> 1] = lw;
            }
        }
    }
}

// ---------------------------------------------------------------------------
// mma flash attention, ldmatrix edition. CTA = 128 q-rows x (head, batch).
// Q frags hoisted into registers; K via ldmatrix; V via ldmatrix.trans
// (staged key-major by cp.async, no SIMT transpose).
// ---------------------------------------------------------------------------
#define ASTR 36
#define AQH 0
#define AQL (128*ASTR)
#define AKH (2*128*ASTR)
#define AKL (AKH + 64*ASTR)
#define AVH (AKH + 2*64*ASTR)
#define AVL (AKH + 3*64*ASTR)
#define ATT_SMEM ((2*128*ASTR + 4*64*ASTR)*4)   // 73728 B

__global__ __launch_bounds__(256)
void attn_mma(const __nv_bfloat16* __restrict__ qh, const __nv_bfloat16* __restrict__ ql,
              uint32_t* __restrict__ oh, uint32_t* __restrict__ ol)
{
    uint32_t* sm = (uint32_t*)dynsm;
    const uint32_t sb = smem_u32(sm);
    const int tid = threadIdx.x, warp = tid >> 5, lane = tid & 31;
    const int g = lane >> 2, c = lane & 3;
    const int qt = (int)gridDim.x - 1 - (int)blockIdx.x;
    const int h = blockIdx.y, b = blockIdx.z;
    const long rowbase = (long)b * SS;
    const int qoff = h << 6;

    const int alr = lane & 15, alw = (lane >> 4) * 4;
    const int blr = (lane & 7) + ((lane >> 4) << 3);
    const int blw = ((lane >> 3) & 1) * 4;
    // V trans-ldmatrix lane coords
    const int vlr = ((lane >> 3) & 1) * 8 + (lane & 7);   // key row within 16
    const int vlw = (lane >> 4) * 4;                       // dh-half word

    // stage Q (128 rows x 64, hi+lo)
    #pragma unroll
    for (int p = 0; p < 2; p++) {
        const __nv_bfloat16* src = p ? ql : qh;
        uint32_t dst = sb + (p ? AQL : AQH) * 4;
        #pragma unroll
        for (int i = 0; i < 4; i++) {
            int id = tid + 256 * i;
            int row = id >> 3, ch = id & 7;
            cpa16(dst + (uint32_t)(row * ASTR + ch * 4) * 4,
                  src + (rowbase + qt * 128 + row) * 1536 + qoff + ch * 8);
        }
    }
    asm volatile("cp.async.commit_group;");
    asm volatile("cp.async.wait_group 0;");
    __syncthreads();

    // hoist Q fragments into registers (4 k-chunks x hi/lo)
    uint32_t Qh[4][4], Ql[4][4];
    #pragma unroll
    for (int kk = 0; kk < 4; kk++) {
        uint32_t qo = (uint32_t)((warp*16 + alr) * ASTR + kk*8 + alw) * 4;
        ldm4(Qh[kk], sb + AQH*4 + qo);
        ldm4(Ql[kk], sb + AQL*4 + qo);
    }

    float m0 = -1e30f, m1 = -1e30f, l0 = 0.f, l1 = 0.f;
    float O[8][4] = {};
    const int nk = 2 * qt + 2;
    const int rbase = qt * 128 + warp * 16;

    for (int kt = 0; kt < nk; kt++) {
        // stage K and V rows (hi+lo) via cp.async
        #pragma unroll
        for (int i = 0; i < 8; i++) {
            int id = tid + 256 * i;
            int p  = (id >> 9) & 1;           // hi/lo plane
            int kv = id >> 10;                // 0=K, 1=V
            int rem = id & 511;
            int row = rem >> 3, ch = rem & 7;
            const __nv_bfloat16* src = p ? ql : qh;
            uint32_t base = kv ? (p ? AVL : AVH) : (p ? AKL : AKH);
            cpa16(sb + (uint32_t)(base + row * ASTR + ch * 4) * 4,
                  src + (rowbase + kt * 64 + row) * 1536 + (kv ? 1024 : 512) + qoff + ch * 8);
        }
        asm volatile("cp.async.commit_group;");
        asm volatile("cp.async.wait_group 0;");
        __syncthreads();

        // ---- S = Q K^T (16x64 per warp), 3-term ----
        float sacc[8][4] = {};
        #pragma unroll
        for (int kk = 0; kk < 4; kk++) {
            #pragma unroll
            for (int pr = 0; pr < 4; pr++) {
                uint32_t bh[4], bl[4];
                uint32_t bo = (uint32_t)((pr*16 + blr) * ASTR + kk*8 + blw) * 4;
                ldm4(bh, sb + AKH*4 + bo);
                ldm4(bl, sb + AKL*4 + bo);
                #pragma unroll
                for (int sub = 0; sub < 2; sub++) {
                    int nt = pr * 2 + sub;
                    mma_bf16(sacc[nt], Qh[kk], bh + 2*sub);
                    mma_bf16(sacc[nt], Qh[kk], bl + 2*sub);
                    mma_bf16(sacc[nt], Ql[kk], bh + 2*sub);
                }
            }
        }

        // ---- mask + online softmax ----
        const float scale = 0.125f;
        const bool diag = (kt >= 2 * qt);
        const int row0 = rbase + g, row1 = rbase + g + 8;
        const int colb = kt * 64 + 2 * c;
        float rm0 = -1e30f, rm1 = -1e30f;
        #pragma unroll
        for (int nt = 0; nt < 8; nt++) {
            int c0 = colb + nt * 8;
            float v0 = sacc[nt][0] * scale, v1 = sacc[nt][1] * scale;
            float v2 = sacc[nt][2] * scale, v3 = sacc[nt][3] * scale;
            if (diag) {
                if (c0     > row0) v0 = -1e30f;
                if (c0 + 1 > row0) v1 = -1e30f;
                if (c0     > row1) v2 = -1e30f;
                if (c0 + 1 > row1) v3 = -1e30f;
            }
            sacc[nt][0] = v0; sacc[nt][1] = v1; sacc[nt][2] = v2; sacc[nt][3] = v3;
            rm0 = fmaxf(rm0, fmaxf(v0, v1));
            rm1 = fmaxf(rm1, fmaxf(v2, v3));
        }
        #pragma unroll
        for (int o = 1; o < 4; o <<= 1) {
            rm0 = fmaxf(rm0, __shfl_xor_sync(0xffffffffu, rm0, o));
            rm1 = fmaxf(rm1, __shfl_xor_sync(0xffffffffu, rm1, o));
        }
        float nm0 = fmaxf(m0, rm0), nm1 = fmaxf(m1, rm1);
        float sf0 = __expf(m0 - nm0), sf1 = __expf(m1 - nm1);
        m0 = nm0; m1 = nm1;
        float rs0 = 0.f, rs1 = 0.f;
        #pragma unroll
        for (int nt = 0; nt < 8; nt++) {
            float p0 = __expf(sacc[nt][0] - nm0);
            float p1 = __expf(sacc[nt][1] - nm0);
            float p2 = __expf(sacc[nt][2] - nm1);
            float p3 = __expf(sacc[nt][3] - nm1);
            sacc[nt][0] = p0; sacc[nt][1] = p1; sacc[nt][2] = p2; sacc[nt][3] = p3;
            rs0 += p0 + p1; rs1 += p2 + p3;
        }
        #pragma unroll
        for (int o = 1; o < 4; o <<= 1) {
            rs0 += __shfl_xor_sync(0xffffffffu, rs0, o);
            rs1 += __shfl_xor_sync(0xffffffffu, rs1, o);
        }
        l0 = l0 * sf0 + rs0;
        l1 = l1 * sf1 + rs1;
        #pragma unroll
        for (int nt = 0; nt < 8; nt++) {
            O[nt][0] *= sf0; O[nt][1] *= sf0;
            O[nt][2] *= sf1; O[nt][3] *= sf1;
        }

        // ---- O += P V  (P in regs; V B-frags via ldmatrix.trans) ----
        #pragma unroll
        for (int kk = 0; kk < 4; kk++) {
            uint32_t ah[4], al[4];
            split2(sacc[2*kk][0],   sacc[2*kk][1],   ah[0], al[0]);
            split2(sacc[2*kk][2],   sacc[2*kk][3],   ah[1], al[1]);
            split2(sacc[2*kk+1][0], sacc[2*kk+1][1], ah[2], al[2]);
            split2(sacc[2*kk+1][2], sacc[2*kk+1][3], ah[3], al[3]);
            #pragma unroll
            for (int pr = 0; pr < 4; pr++) {
                uint32_t bh[4], bl[4];
                uint32_t vo = (uint32_t)((kk*16 + vlr) * ASTR + pr*8 + vlw) * 4;
                ldm4t(bh, sb + AVH*4 + vo);
                ldm4t(bl, sb + AVL*4 + vo);
                #pragma unroll
                for (int sub = 0; sub < 2; sub++) {
                    int nt = pr * 2 + sub;
                    mma_bf16(O[nt], ah, bh + 2*sub);
                    mma_bf16(O[nt], ah, bl + 2*sub);
                    mma_bf16(O[nt], al, bh + 2*sub);
                }
            }
        }
        __syncthreads();
    }

    // ---- epilogue: O/l -> hi/lo planes ----
    float inv0 = 1.0f / l0, inv1 = 1.0f / l1;
    long grow0 = rowbase + rbase + g;
    #pragma unroll
    for (int nt = 0; nt < 8; nt++) {
        int col = qoff + nt * 8 + 2 * c;
        uint32_t hw, lw;
        split2(O[nt][0] * inv0, O[nt][1] * inv0, hw, lw);
        oh[(grow0 * DD + col) >> 1] = hw;
        ol[(grow0 * DD + col) >> 1] = lw;
        split2(O[nt][2] * inv1, O[nt][3] * inv1, hw, lw);
        oh[((grow0 + 8) * DD + col) >> 1] = hw;
        ol[((grow0 + 8) * DD + col) >> 1] = lw;
    }
}

// ---------------------------------------------------------------------------
extern "C" void kernel_launch(void* const* d_in, const int* in_sizes, int n_in,
                              void* d_out, int out_size)
{
    const int*   x    = (const int*)  d_in[0];
    const float* emb  = (const float*)d_in[1];
    const float* pe   = (const float*)d_in[2];
    const float* Wqkv = (const float*)d_in[3];
    const float* Wo   = (const float*)d_in[4];
    const float* bo   = (const float*)d_in[5];
    const float* g1   = (const float*)d_in[6];
    const float* b1   = (const float*)d_in[7];
    const float* g2   = (const float*)d_in[8];
    const float* b2   = (const float*)d_in[9];
    const float* W1   = (const float*)d_in[10];
    const float* bf1  = (const float*)d_in[11];
    const float* W2   = (const float*)d_in[12];
    const float* bf2  = (const float*)d_in[13];
    const float* gf   = (const float*)d_in[14];
    const float* bfp  = (const float*)d_in[15];
    const float* Wout = (const float*)d_in[16];
    const float* bfc  = (const float*)d_in[17];
    float* out = (float*)d_out;

    float *h, *t;
    cudaGetSymbolAddress((void**)&h, g_h);
    cudaGetSymbolAddress((void**)&t, g_t);
    __nv_bfloat16 *hh, *hl, *qh, *ql, *oh, *ol, *fh, *fl, *th, *tl;
    cudaGetSymbolAddress((void**)&hh, g_hh);  cudaGetSymbolAddress((void**)&hl, g_hl);
    cudaGetSymbolAddress((void**)&qh, g_qh);  cudaGetSymbolAddress((void**)&ql, g_ql);
    cudaGetSymbolAddress((void**)&oh, g_oh);  cudaGetSymbolAddress((void**)&ol, g_ol);
    cudaGetSymbolAddress((void**)&fh, g_fh);  cudaGetSymbolAddress((void**)&fl, g_fl);
    cudaGetSymbolAddress((void**)&th, g_th);  cudaGetSymbolAddress((void**)&tl, g_tl);
    __nv_bfloat16 *qkvTh, *qkvTl, *woTh, *woTl, *w1Th, *w1Tl, *w2Th, *w2Tl, *outTh, *outTl;
    cudaGetSymbolAddress((void**)&qkvTh, g_qkvT_h);
    cudaGetSymbolAddress((void**)&qkvTl, g_qkvT_l);
    cudaGetSymbolAddress((void**)&woTh,  g_woT_h);
    cudaGetSymbolAddress((void**)&woTl,  g_woT_l);
    cudaGetSymbolAddress((void**)&w1Th,  g_w1T_h);
    cudaGetSymbolAddress((void**)&w1Tl,  g_w1T_l);
    cudaGetSymbolAddress((void**)&w2Th,  g_w2T_h);
    cudaGetSymbolAddress((void**)&w2Tl,  g_w2T_l);
    cudaGetSymbolAddress((void**)&outTh, g_outT_h);
    cudaGetSymbolAddress((void**)&outTl, g_outT_l);

    cudaFuncSetAttribute(attn_mma, cudaFuncAttributeMaxDynamicSharedMemorySize, ATT_SMEM);
    cudaFuncSetAttribute(gemm_bf16<0,0>, cudaFuncAttributeMaxDynamicSharedMemorySize, GEMM_SMEM);
    cudaFuncSetAttribute(gemm_bf16<0,1>, cudaFuncAttributeMaxDynamicSharedMemorySize, GEMM_SMEM);
    cudaFuncSetAttribute(gemm_bf16<1,1>, cudaFuncAttributeMaxDynamicSharedMemorySize, GEMM_SMEM);

    wprep_k<<<dim3(3*DD/32, DD/32, LL), 256>>>(Wqkv, qkvTh, qkvTl, DD, 3*DD);
    wprep_k<<<dim3(DD/32,   DD/32, LL), 256>>>(Wo,   woTh,  woTl,  DD, DD);
    wprep_k<<<dim3(FF/32,   DD/32, LL), 256>>>(W1,   w1Th,  w1Tl,  DD, FF);
    wprep_k<<<dim3(DD/32,   FF/32, LL), 256>>>(W2,   w2Th,  w2Tl,  FF, DD);
    wprep_k<<<dim3(VV/32,   DD/32, 1 ), 256>>>(Wout, outTh, outTl, DD, VV);

    embed_k<<<ROWS, 128>>>(x, emb, pe, h, (uint32_t*)hh, (uint32_t*)hl);

    for (int l = 0; l < LL; l++) {
        gemm_bf16<0,1><<<dim3(32, 12), 256, GEMM_SMEM>>>(
            hh, hl, qkvTh + (long)l * 3*DD*DD, qkvTl + (long)l * 3*DD*DD,
            nullptr, nullptr, (uint32_t*)qh, (uint32_t*)ql, ROWS, 3*DD, DD);
        attn_mma<<<dim3(SS/128, HH, BB), 256, ATT_SMEM>>>(
            qh, ql, (uint32_t*)oh, (uint32_t*)ol);
        gemm_bf16<0,0><<<dim3(32, 4), 256, GEMM_SMEM>>>(
            oh, ol, woTh + (long)l * DD*DD, woTl + (long)l * DD*DD,
            bo + l * DD, t, nullptr, nullptr, ROWS, DD, DD);
        add_ln_k<<<ROWS, 128>>>(t, h, g1 + l * DD, b1 + l * DD,
                                h, (uint32_t*)hh, (uint32_t*)hl);
        gemm_bf16<1,1><<<dim3(32, 16), 256, GEMM_SMEM>>>(
            hh, hl, w1Th + (long)l * FF*DD, w1Tl + (long)l * FF*DD,
            bf1 + l * FF, nullptr, (uint32_t*)fh, (uint32_t*)fl, ROWS, FF, DD);
        gemm_bf16<0,0><<<dim3(32, 4), 256, GEMM_SMEM>>>(
            fh, fl, w2Th + (long)l * DD*FF, w2Tl + (long)l * DD*FF,
            bf2 + l * DD, t, nullptr, nullptr, ROWS, DD, FF);
        add_ln_k<<<ROWS, 128>>>(t, h, g2 + l * DD, b2 + l * DD,
                                h, (uint32_t*)hh, (uint32_t*)hl);
    }

    add_ln_k<<<ROWS, 128>>>(h, nullptr, gf, bfp, t, (uint32_t*)th, (uint32_t*)tl);
    gemm_bf16<0,0><<<dim3(32, 250), 256, GEMM_SMEM>>>(
        th, tl, outTh, outTl, bfc, out, nullptr, nullptr, ROWS, VV, DD);
}